// round 13
// baseline (speedup 1.0000x reference)
#include <cuda_runtime.h>
#include <cuda_bf16.h>
#include <cuda_fp16.h>
#include <cstdint>
#include <math.h>

#define MM 4
#define N_ITEM 40000
#define N_USER 10000
#define NN 50000
#define DD 128
#define DX 64
#define EE 400000
#define BB 4096

// ---------------- scratch (device globals; allocation-free) ----------------
__device__ __nv_bfloat16 g_xb [(long)MM*NN*256];   // x hi|lo planes
__device__ __nv_bfloat16 g_hb [(long)MM*NN*256];   // h hi|lo planes
__device__ __nv_bfloat16 g_ufb[(long)N_USER*256];
__device__ __nv_bfloat16 g_uwb[MM*128*384];
__device__ __nv_bfloat16 g_cwb[MM*128*384];
__device__ __nv_bfloat16 g_l1b[MM*64*384];
__device__ __nv_bfloat16 g_g1b[MM*64*384];
__device__ float  g_xt  [MM*NN*DD];
__device__ __half g_xt16[(long)MM*NN*DD];          // fp16 xt for logits
__device__ float g_agg [MM*NN*DD];   // fp32 temp (usergemm out)
__device__ float g_xh  [MM*NN*DX];
__device__ float g_reps[MM*NN*DX];
__device__ float g_w   [EE];         // logits in CSR position order
__device__ float g_deg [NN];
__device__ float g_dinv[NN];
__device__ int   g_degD[NN];
__device__ int   g_off [NN+1];
__device__ int   g_cur [NN];
__device__ int   g_srcs[EE];         // src node per CSR position
__device__ int   g_dsts[EE];         // dst node per CSR position
__device__ float g_kmod[MM*DX];
__device__ float g_kp  [MM*DX];
__device__ float g_vp  [MM*DX];

__device__ __forceinline__ float lrelu(float x){ return x > 0.f ? x : 0.01f*x; }
__device__ __forceinline__ float wsum(float v){
  #pragma unroll
  for (int o = 16; o; o >>= 1) v += __shfl_xor_sync(0xffffffffu, v, o);
  return v;
}
__device__ __forceinline__ float wmaxr(float v){
  #pragma unroll
  for (int o = 16; o; o >>= 1) v = fmaxf(v, __shfl_xor_sync(0xffffffffu, v, o));
  return v;
}
__device__ __forceinline__ __nv_bfloat16 hilo(float v, bool lo){
  __nv_bfloat16 h = __float2bfloat16(v);
  return lo ? __float2bfloat16(v - __bfloat162float(h)) : h;
}
__device__ __forceinline__ void put4(__nv_bfloat16* dst, float4 v, float rn){
  float a0=v.x*rn, a1=v.y*rn, a2=v.z*rn, a3=v.w*rn;
  __nv_bfloat16 h[4] = {__float2bfloat16(a0),__float2bfloat16(a1),
                        __float2bfloat16(a2),__float2bfloat16(a3)};
  __nv_bfloat16 l[4] = {
    __float2bfloat16(a0-__bfloat162float(h[0])), __float2bfloat16(a1-__bfloat162float(h[1])),
    __float2bfloat16(a2-__bfloat162float(h[2])), __float2bfloat16(a3-__bfloat162float(h[3]))};
  *(uint2*)dst = *(uint2*)h;
  *(uint2*)(dst+128) = *(uint2*)l;
}

// ---------------- MMA + cp.async primitives ----------------
__device__ __forceinline__ void mma16816(float* d, const uint32_t* a, const uint32_t* b){
  asm volatile("mma.sync.aligned.m16n8k16.row.col.f32.bf16.bf16.f32 "
    "{%0,%1,%2,%3}, {%4,%5,%6,%7}, {%8,%9}, {%0,%1,%2,%3};"
    : "+f"(d[0]), "+f"(d[1]), "+f"(d[2]), "+f"(d[3])
    : "r"(a[0]), "r"(a[1]), "r"(a[2]), "r"(a[3]), "r"(b[0]), "r"(b[1]));
}
__device__ __forceinline__ uint32_t smem_u32(const void* p){
  uint32_t a;
  asm("{ .reg .u64 t; cvta.to.shared.u64 t, %1; cvt.u32.u64 %0, t; }" : "=r"(a) : "l"(p));
  return a;
}
__device__ __forceinline__ void cpasync16(uint32_t sdst, const void* gsrc, bool pred){
  int sz = pred ? 16 : 0;
  asm volatile("cp.async.cg.shared.global [%0], [%1], 16, %2;"
               :: "r"(sdst), "l"(gsrc), "r"(sz));
}
#define CP_COMMIT() asm volatile("cp.async.commit_group;" ::: "memory")
#define CP_WAIT1()  asm volatile("cp.async.wait_group 1;" ::: "memory")
#define CP_WAIT0()  asm volatile("cp.async.wait_group 0;" ::: "memory")

// ---- bf16 HMMA GEMM, K_eff=384 (=3-term split), cp.async double-buffered ---
// A: [M,256] hi|lo.  Bw: [BN,384] = [Bh|Bl|Bh].  C fp32 [M,BN].
// EPI 0: none | 1: tanh(+bias) | 2: lrelu(+bias)+add | 3: lrelu(+bias+add)
// EPI 4: none, dual-store fp32 C + fp16 C16
template<int BN, int EPI>
__global__ void __launch_bounds__(256,2) k_bgemm(
    const __nv_bfloat16* __restrict__ A, const __nv_bfloat16* __restrict__ Bw,
    float* __restrict__ C, __half* __restrict__ C16, int M,
    long sA, long sB, long sC,
    const float* __restrict__ bias, long sBias,
    const float* __restrict__ add, long sAdd)
{
  constexpr int P = 72;
  constexpr int ASZ = 128*P, BSZ = BN*P, STG = ASZ + BSZ;
  constexpr int NF = BN/16;
  constexpr int LB = BN/32;
  extern __shared__ __nv_bfloat16 sm[];
  int z = blockIdx.z;
  A += (long)z*sA; Bw += (long)z*sB; C += (long)z*sC;
  if (EPI == 4) C16 += (long)z*sC;
  if (EPI == 1 || EPI == 2 || EPI == 3) bias += (long)z*sBias;
  if (EPI == 2 || EPI == 3)             add  += (long)z*sAdd;
  int m0 = blockIdx.x*128;
  int tid = threadIdx.x, lane = tid & 31, wid = tid >> 5;
  uint32_t smb = smem_u32(sm);

  auto aload = [&](int t, int buf){
    int cb = ((t & 4) << 5) | ((t & 1) << 6);   // {0,64,0,64,128,192}
    #pragma unroll
    for (int i = 0; i < 4; i++){
      int idx = tid + i*256;
      int r = idx >> 3, c8 = (idx & 7)*8;
      bool inb = (m0 + r) < M;
      const __nv_bfloat16* gp = A + (inb ? ((long)(m0+r)*256 + cb + c8) : 0);
      cpasync16(smb + (uint32_t)(buf*STG + r*P + c8)*2, gp, inb);
    }
    #pragma unroll
    for (int i = 0; i < LB; i++){
      int idx = tid + i*256;
      int r = idx >> 3, c8 = (idx & 7)*8;
      cpasync16(smb + (uint32_t)(buf*STG + ASZ + r*P + c8)*2,
                Bw + (long)r*384 + t*64 + c8, true);
    }
  };

  aload(0, 0);
  CP_COMMIT();

  int wm = (wid & 3) << 5;
  int wn = (wid >> 2) * (BN/2);
  int lr = lane >> 2, lc = (lane & 3) << 1;
  float acc[2][NF][4];
  #pragma unroll
  for (int i = 0; i < 2; i++)
    #pragma unroll
    for (int j = 0; j < NF; j++)
      #pragma unroll
      for (int q = 0; q < 4; q++) acc[i][j][q] = 0.f;

  #pragma unroll
  for (int t = 0; t < 6; t++){
    if (t < 5){ aload(t+1, (t+1)&1); CP_COMMIT(); CP_WAIT1(); }
    else      { CP_WAIT0(); }
    __syncthreads();
    const __nv_bfloat16* As = sm + (t&1)*STG;
    const __nv_bfloat16* Bs = As + ASZ;
    #pragma unroll
    for (int k0 = 0; k0 < 64; k0 += 16){
      int kk = k0 + lc;
      uint32_t a[2][4];
      #pragma unroll
      for (int mi = 0; mi < 2; mi++){
        int r = wm + mi*16 + lr;
        a[mi][0] = *(const uint32_t*)(As + r*P + kk);
        a[mi][1] = *(const uint32_t*)(As + (r+8)*P + kk);
        a[mi][2] = *(const uint32_t*)(As + r*P + kk + 8);
        a[mi][3] = *(const uint32_t*)(As + (r+8)*P + kk + 8);
      }
      #pragma unroll
      for (int nf = 0; nf < NF; nf++){
        int n = wn + nf*8 + lr;
        uint32_t b[2];
        b[0] = *(const uint32_t*)(Bs + n*P + kk);
        b[1] = *(const uint32_t*)(Bs + n*P + kk + 8);
        mma16816(acc[0][nf], a[0], b);
        mma16816(acc[1][nf], a[1], b);
      }
    }
    __syncthreads();
  }

  #pragma unroll
  for (int mi = 0; mi < 2; mi++){
    #pragma unroll
    for (int h = 0; h < 2; h++){
      int row = m0 + wm + mi*16 + lr + h*8;
      if (row >= M) continue;
      #pragma unroll
      for (int nf = 0; nf < NF; nf++){
        int n = wn + nf*8 + lc;
        float x0 = acc[mi][nf][h*2+0];
        float x1 = acc[mi][nf][h*2+1];
        if (EPI == 1){ x0 = tanhf(x0 + bias[n]); x1 = tanhf(x1 + bias[n+1]); }
        else if (EPI == 2){
          x0 = lrelu(x0 + bias[n])   + add[(long)row*BN + n];
          x1 = lrelu(x1 + bias[n+1]) + add[(long)row*BN + n+1];
        } else if (EPI == 3){
          x0 = lrelu(x0 + bias[n]   + add[(long)row*BN + n]);
          x1 = lrelu(x1 + bias[n+1] + add[(long)row*BN + n+1]);
        }
        *(float2*)(C + (long)row*BN + n) = make_float2(x0, x1);
        if (EPI == 4)
          *(__half2*)(C16 + (long)row*BN + n) = __float22half2_rn(make_float2(x0, x1));
      }
    }
  }
}

// ------- k_prep: items normalize->bf16 planes + all input conversions -------
#define CV0 (N_USER*256)
#define WU  (MM*128*384)
#define WL  (MM*64*384)
#define CV1 (CV0 + WU)
#define CV2 (CV1 + WU)
#define CV3 (CV2 + WL)
#define CV4 (CV3 + WL)
__global__ void k_prep(const float* __restrict__ feats, const float* __restrict__ uf,
                       const float* __restrict__ userW, const float* __restrict__ convW,
                       const float* __restrict__ lin1W, const float* __restrict__ g1W){
  long g = (long)blockIdx.x*256 + threadIdx.x;
  if (g < NN){ g_deg[g] = 0.f; g_degD[g] = 0; }
  long w = g >> 5; int lane = (int)(g & 31);
  if (w < (long)MM*N_ITEM){
    int m = (int)(w / N_ITEM), i = (int)(w - (long)m*N_ITEM);
    const float* in = feats + ((long)m*N_ITEM + i)*DD;
    float4 v = *(const float4*)(in + lane*4);
    float ss = wsum(v.x*v.x + v.y*v.y + v.z*v.z + v.w*v.w);
    float rn = 1.f / fmaxf(sqrtf(ss), 1e-12f);
    put4(g_xb + ((long)m*NN + i)*256 + lane*4, v, rn);
  }
  if (g < CV0){
    int r = (int)(g >> 8), c = (int)(g & 255);
    g_ufb[g] = hilo(uf[r*128 + (c & 127)], c >= 128);
  } else if (g < CV1){
    long j = g - CV0;
    int m = (int)(j/49152); int r2 = (int)(j%49152);
    int n = r2/384, kp = r2%384, sel = kp>>7, kk = kp&127;
    g_uwb[j] = hilo(userW[(long)m*16384 + n*128 + kk], sel == 1);
  } else if (g < CV2){
    long j = g - CV1;
    int m = (int)(j/49152); int r2 = (int)(j%49152);
    int n = r2/384, kp = r2%384, sel = kp>>7, kk = kp&127;
    g_cwb[j] = hilo(convW[(long)m*16384 + kk*128 + n], sel == 1);
  } else if (g < CV3){
    long j = g - CV2;
    int m = (int)(j/24576); int r2 = (int)(j%24576);
    int n = r2/384, kp = r2%384, sel = kp>>7, kk = kp&127;
    g_l1b[j] = hilo(lin1W[(long)m*8192 + n*128 + kk], sel == 1);
  } else if (g < CV4){
    long j = g - CV3;
    int m = (int)(j/24576); int r2 = (int)(j%24576);
    int n = r2/384, kp = r2%384, sel = kp>>7, kk = kp&127;
    g_g1b[j] = hilo(g1W[(long)m*8192 + n*128 + kk], sel == 1);
  }
}
__global__ void k_norm_users(){
  int g = blockIdx.x*256 + threadIdx.x;
  int w = g >> 5, lane = g & 31;
  if (w >= MM*N_USER) return;
  int m = w / N_USER, i = w - m*N_USER;
  const float* in = g_agg + ((long)m*N_USER + i)*DD;
  float4 v = *(const float4*)(in + lane*4);
  float ss = wsum(v.x*v.x + v.y*v.y + v.z*v.z + v.w*v.w);
  float rn = 1.f / fmaxf(sqrtf(ss), 1e-12f);
  put4(g_xb + ((long)m*NN + N_ITEM + i)*256 + lane*4, v, rn);
}

// ---------------- CSR build ----------------
__global__ void k_deg(const int* __restrict__ src, const int* __restrict__ dst){
  int e = blockIdx.x*256 + threadIdx.x;
  if (e < EE){ atomicAdd(&g_deg[src[e]], 1.f); atomicAdd(&g_degD[dst[e]], 1); }
}
#define SCAN_T 1024
__global__ void __launch_bounds__(SCAN_T) k_scan(){
  __shared__ int ps[SCAN_T];
  int t = threadIdx.x;
  const int C = (NN + SCAN_T - 1)/SCAN_T;
  int lo = t*C, hi = lo+C < NN ? lo+C : NN;
  int s = 0;
  for (int i = lo; i < hi; i++){
    s += g_degD[i];
    float d = g_deg[i];
    g_dinv[i] = d > 0.f ? 1.f/sqrtf(d) : 0.f;
  }
  ps[t] = s; __syncthreads();
  for (int off = 1; off < SCAN_T; off <<= 1){
    int v = (t >= off) ? ps[t-off] : 0;
    __syncthreads();
    ps[t] += v;
    __syncthreads();
  }
  int run = t ? ps[t-1] : 0;
  for (int i = lo; i < hi; i++){ int d = g_degD[i]; g_off[i] = run; g_cur[i] = run; run += d; }
  if (t == SCAN_T-1) g_off[NN] = run;
}
__global__ void k_scatter(const int* __restrict__ src, const int* __restrict__ dst){
  int e = blockIdx.x*256 + threadIdx.x;
  if (e < EE){
    int d = dst[e];
    int p = atomicAdd(&g_cur[d], 1);
    g_srcs[p] = src[e];
    g_dsts[p] = d;
  }
}

// ------- edge logits (CSR order, fp16 rows): 8 lanes/edge, 4 edges/warp -----
__global__ void __launch_bounds__(256) k_ipwm(const __half* __restrict__ xt16){
  int gw = (blockIdx.x << 3) | (threadIdx.x >> 5);
  int lane = threadIdx.x & 31;
  int sub = lane >> 3, l8 = lane & 7;
  int i = (gw << 2) | sub;
  if (i >= EE) return;
  int s = g_srcs[i], d = g_dsts[i];
  const __half* ps = xt16 + (long)s*DD;
  const __half* pd = xt16 + (long)d*DD;
  float acc = 0.f;
  #pragma unroll
  for (int c = 0; c < 2; c++){
    uint4 a4 = *(const uint4*)(ps + c*64 + l8*8);
    uint4 b4 = *(const uint4*)(pd + c*64 + l8*8);
    const __half2* ah = (const __half2*)&a4;
    const __half2* bh = (const __half2*)&b4;
    #pragma unroll
    for (int j = 0; j < 4; j++){
      float2 a = __half22float2(ah[j]);
      float2 b = __half22float2(bh[j]);
      acc += b.x*lrelu(a.x) + b.y*lrelu(a.y);
    }
  }
  #pragma unroll
  for (int o = 4; o; o >>= 1) acc += __shfl_xor_sync(0xffffffffu, acc, o);
  if (l8 == 0){
    float di = g_dinv[s];
    g_w[i] = acc / (1.f + expf(-di*acc));
  }
}

// fused per-dst segment softmax + aggregate + bias + l2norm + lrelu -> bf16 h
__global__ void __launch_bounds__(256) k_nodeagg(const float* __restrict__ xt,
                                                 const float* __restrict__ cb,
                                                 __nv_bfloat16* __restrict__ hb){
  int g = blockIdx.x*256 + threadIdx.x;
  int n = g >> 5, lane = g & 31;
  if (n >= NN) return;
  int o0 = g_off[n], o1 = g_off[n+1];
  float wm = -3.4e38f;
  for (int i = o0 + lane; i < o1; i += 32) wm = fmaxf(wm, g_w[i]);
  wm = wmaxr(wm);
  float es = 0.f;
  for (int i = o0 + lane; i < o1; i += 32) es += expf(g_w[i] - wm);
  es = wsum(es);
  float rs = 1.f / (es + 1e-16f);
  float4 acc = make_float4(0,0,0,0);
  for (int i = o0; i < o1; i++){
    float att = expf(g_w[i] - wm) * rs;
    float4 a = *(const float4*)(xt + (long)g_srcs[i]*DD + lane*4);
    acc.x += att*a.x; acc.y += att*a.y; acc.z += att*a.z; acc.w += att*a.w;
  }
  float4 b4 = *(const float4*)(cb + lane*4);
  acc.x += b4.x; acc.y += b4.y; acc.z += b4.z; acc.w += b4.w;
  float ss = acc.x*acc.x + acc.y*acc.y + acc.z*acc.z + acc.w*acc.w;
  ss = wsum(ss);
  float rn = 1.f / fmaxf(sqrtf(ss), 1e-12f);
  float4 o;
  o.x = lrelu(acc.x*rn); o.y = lrelu(acc.y*rn);
  o.z = lrelu(acc.z*rn); o.w = lrelu(acc.w*rn);
  put4(hb + (long)n*256 + lane*4, o, 1.f);
}

// ---------------- tail ----------------
__global__ void k_mean(float* __restrict__ out_rep){
  int i = blockIdx.x*256 + threadIdx.x;
  if (i < MM*DX) g_kmod[i] = 0.f;
  if (i < NN*DX)
    out_rep[i] = 0.25f * (g_reps[i] + g_reps[(long)NN*DX + i]
                        + g_reps[2L*NN*DX + i] + g_reps[3L*NN*DX + i]);
}
__global__ void __launch_bounds__(64) k_kmod(const int* __restrict__ pi){
  int m = blockIdx.y, j = threadIdx.x;
  int b0 = blockIdx.x * 64;
  float acc = 0.f;
  #pragma unroll 4
  for (int t = 0; t < 64; t++){
    int p = pi[b0 + t];
    acc += g_reps[((long)m*NN + p)*DX + j];
  }
  atomicAdd(&g_kmod[m*DX + j], acc);
}
__global__ void k_kpvp(const float* __restrict__ kW, const float* __restrict__ vW){
  int tid = threadIdx.x;
  int m = tid >> 6, j = tid & 63;
  float s1 = 0.f, s2 = 0.f;
  #pragma unroll 8
  for (int k = 0; k < DX; k++){
    float km = g_kmod[m*DX + k] * (1.f/BB);
    s1 += km * kW[j*DX + k];
    s2 += km * vW[j*DX + k];
  }
  g_kp[m*DX + j] = s1;
  g_vp[m*DX + j] = s2;
}
__global__ void __launch_bounds__(64) k_final(
    const float* __restrict__ rep,
    const int* __restrict__ un, const int* __restrict__ pi, const int* __restrict__ ni,
    const float* __restrict__ qW,
    const float* __restrict__ mpW1, const float* __restrict__ mpb1,
    const float* __restrict__ mpW2, const float* __restrict__ mpb2,
    float* __restrict__ out_pos, float* __restrict__ out_neg, float* __restrict__ out_pred)
{
  int b = blockIdx.x, j = threadIdx.x;
  __shared__ float su[DX], sq[DX], sa[DX], sp[DX], sn[DX], sc[MM], red[DX];
  su[j] = rep[(long)un[b]*DX + j];
  sp[j] = rep[(long)pi[b]*DX + j];
  sn[j] = rep[(long)ni[b]*DX + j];
  __syncthreads();
  float q = 0.f;
  #pragma unroll 8
  for (int k = 0; k < DX; k++) q += su[k] * qW[j*DX + k];
  sq[j] = q;
  __syncthreads();
  if (j < MM){
    float s = 0.f;
    #pragma unroll 8
    for (int k = 0; k < DX; k++) s += sq[k] * g_kp[j*DX + k];
    sc[j] = s * 0.125f;
  }
  __syncthreads();
  float mx = fmaxf(fmaxf(sc[0], sc[1]), fmaxf(sc[2], sc[3]));
  float e0 = expf(sc[0]-mx), e1 = expf(sc[1]-mx), e2 = expf(sc[2]-mx), e3 = expf(sc[3]-mx);
  float es = e0 + e1 + e2 + e3;
  float av = (e0*g_vp[0*DX+j] + e1*g_vp[1*DX+j] + e2*g_vp[2*DX+j] + e3*g_vp[3*DX+j]) / es;
  sa[j] = av;
  red[j] = av * sp[j];
  __syncthreads();
  for (int s = 32; s > 0; s >>= 1){ if (j < s) red[j] += red[j+s]; __syncthreads(); }
  if (j == 0) out_pos[b] = red[0];
  __syncthreads();
  red[j] = av * sn[j];
  __syncthreads();
  for (int s = 32; s > 0; s >>= 1){ if (j < s) red[j] += red[j+s]; __syncthreads(); }
  if (j == 0) out_neg[b] = red[0];
  __syncthreads();
  float h = mpb1[j];
  #pragma unroll 8
  for (int k = 0; k < DX; k++) h += sa[k] * mpW1[j*2*DX + k];
  #pragma unroll 8
  for (int k = 0; k < DX; k++) h += sp[k] * mpW1[j*2*DX + DX + k];
  h = lrelu(h);
  red[j] = h * mpW2[j];
  __syncthreads();
  for (int s = 32; s > 0; s >>= 1){ if (j < s) red[j] += red[j+s]; __syncthreads(); }
  if (j == 0) out_pred[b] = red[0] + mpb2[0];
}

// ---------------- host ----------------
extern "C" void kernel_launch(void* const* d_in, const int* in_sizes, int n_in,
                              void* d_out, int out_size)
{
  const float* feats  = (const float*)d_in[0];
  const float* uf     = (const float*)d_in[1];
  const float* userW  = (const float*)d_in[2];
  const float* userb  = (const float*)d_in[3];
  const float* convW  = (const float*)d_in[4];
  const float* convb  = (const float*)d_in[5];
  const float* lin1W  = (const float*)d_in[6];
  const float* lin1b  = (const float*)d_in[7];
  const float* g1W    = (const float*)d_in[8];
  const float* g1b    = (const float*)d_in[9];
  const float* id_emb = (const float*)d_in[10];
  const float* qW     = (const float*)d_in[11];
  const float* kW     = (const float*)d_in[12];
  const float* vW     = (const float*)d_in[13];
  const float* mpW1   = (const float*)d_in[14];
  const float* mpb1   = (const float*)d_in[15];
  const float* mpW2   = (const float*)d_in[16];
  const float* mpb2   = (const float*)d_in[17];
  const int*   eidx   = (const int*)d_in[18];
  const int*   un     = (const int*)d_in[19];
  const int*   pi     = (const int*)d_in[20];
  const int*   ni     = (const int*)d_in[21];
  const int *src = eidx, *dst = eidx + EE;

  float* out      = (float*)d_out;
  float* out_pos  = out;
  float* out_neg  = out + BB;
  float* out_rep  = out + 2*BB;
  float* out_pred = out + 2*BB + (long)NN*DX;

  void* p;
  cudaGetSymbolAddress(&p, g_xb);   __nv_bfloat16* xb  = (__nv_bfloat16*)p;
  cudaGetSymbolAddress(&p, g_hb);   __nv_bfloat16* hb  = (__nv_bfloat16*)p;
  cudaGetSymbolAddress(&p, g_ufb);  __nv_bfloat16* ufb = (__nv_bfloat16*)p;
  cudaGetSymbolAddress(&p, g_uwb);  __nv_bfloat16* uwb = (__nv_bfloat16*)p;
  cudaGetSymbolAddress(&p, g_cwb);  __nv_bfloat16* cwb = (__nv_bfloat16*)p;
  cudaGetSymbolAddress(&p, g_l1b);  __nv_bfloat16* l1b = (__nv_bfloat16*)p;
  cudaGetSymbolAddress(&p, g_g1b);  __nv_bfloat16* g1bw= (__nv_bfloat16*)p;
  cudaGetSymbolAddress(&p, g_xt);   float* xt    = (float*)p;
  cudaGetSymbolAddress(&p, g_xt16); __half* xt16 = (__half*)p;
  cudaGetSymbolAddress(&p, g_agg);  float* agg   = (float*)p;
  cudaGetSymbolAddress(&p, g_xh);   float* xh    = (float*)p;
  cudaGetSymbolAddress(&p, g_reps); float* reps  = (float*)p;

  const int SMB128 = (128*72 + 128*72)*2*2;   // 73728 B
  const int SMB64  = (128*72 + 64*72)*2*2;    // 55296 B
  cudaFuncSetAttribute(k_bgemm<128,1>, cudaFuncAttributeMaxDynamicSharedMemorySize, SMB128);
  cudaFuncSetAttribute(k_bgemm<128,4>, cudaFuncAttributeMaxDynamicSharedMemorySize, SMB128);
  cudaFuncSetAttribute(k_bgemm<64,2>,  cudaFuncAttributeMaxDynamicSharedMemorySize, SMB64);
  cudaFuncSetAttribute(k_bgemm<64,3>,  cudaFuncAttributeMaxDynamicSharedMemorySize, SMB64);

  // (1) prep
  k_prep<<<(MM*N_ITEM*32)/256, 256>>>(feats, uf, userW, convW, lin1W, g1W);
  // (2) user transform (batched over m)
  {
    dim3 g((N_USER+127)/128, 1, MM);
    k_bgemm<128,1><<<g, 256, SMB128>>>(ufb, uwb, agg, nullptr, N_USER,
                                       0, 128L*384, (long)N_USER*DD, userb, DD, nullptr, 0);
  }
  // (3) users normalize -> bf16 planes
  k_norm_users<<<(MM*N_USER*32 + 255)/256, 256>>>();
  // (4) conv(m=0)  <-- ncu profile slot
  k_bgemm<128,4><<<dim3((NN+127)/128,1,1), 256, SMB128>>>(
      xb, cwb, xt, xt16, NN, 0, 0, 0, nullptr, 0, nullptr, 0);
  // CSR build
  k_deg    <<<(EE+255)/256, 256>>>(src, dst);
  k_scan   <<<1, SCAN_T>>>();
  k_scatter<<<(EE+255)/256, 256>>>(src, dst);

  // per-modality pipeline: conv -> lin1 -> ipwm -> nodeagg -> g1 (L2-hot)
  for (int m = 0; m < MM; m++){
    const __nv_bfloat16* xbm = xb + (long)m*NN*256;
    float*  xtm   = xt   + (long)m*NN*DD;
    __half* xt16m = xt16 + (long)m*NN*DD;
    if (m > 0)
      k_bgemm<128,4><<<dim3((NN+127)/128,1,1), 256, SMB128>>>(
          xbm, cwb + (long)m*128*384, xtm, xt16m, NN, 0, 0, 0, nullptr, 0, nullptr, 0);
    k_bgemm<64,2><<<dim3((NN+127)/128,1,1), 256, SMB64>>>(
        xbm, l1b + (long)m*64*384, xh + (long)m*NN*DX, nullptr, NN,
        0, 0, 0, lin1b + m*DX, 0, id_emb, 0);
    k_ipwm   <<<(EE*8 + 255)/256, 256>>>(xt16m);
    k_nodeagg<<<(NN*32 + 255)/256, 256>>>(xtm, convb + m*DD, hb + (long)m*NN*256);
    k_bgemm<64,3><<<dim3((NN+127)/128,1,1), 256, SMB64>>>(
        hb + (long)m*NN*256, g1bw + (long)m*64*384, reps + (long)m*NN*DX, nullptr, NN,
        0, 0, 0, g1b + m*DX, 0, xh + (long)m*NN*DX, 0);
  }

  k_mean<<<(NN*DX + 255)/256, 256>>>(out_rep);
  k_kmod<<<dim3(BB/64, MM), 64>>>(pi);
  k_kpvp<<<1, 256>>>(kW, vW);
  k_final<<<BB, 64>>>(out_rep, un, pi, ni, qW, mpW1, mpb1, mpW2, mpb2,
                      out_pos, out_neg, out_pred);
}

// round 14
// speedup vs baseline: 1.1026x; 1.1026x over previous
#include <cuda_runtime.h>
#include <cuda_bf16.h>
#include <cuda_fp16.h>
#include <cstdint>
#include <math.h>

#define MM 4
#define N_ITEM 40000
#define N_USER 10000
#define NN 50000
#define DD 128
#define DX 64
#define EE 400000
#define BB 4096

// ---------------- scratch (device globals; allocation-free) ----------------
__device__ __nv_bfloat16 g_xb [(long)MM*NN*256];   // x hi|lo planes
__device__ __nv_bfloat16 g_hb [(long)MM*NN*256];   // h hi|lo planes
__device__ __nv_bfloat16 g_ufb[(long)N_USER*256];
__device__ __nv_bfloat16 g_uwb[MM*128*384];
__device__ __nv_bfloat16 g_cwb[MM*128*384];
__device__ __nv_bfloat16 g_l1b[MM*64*384];
__device__ __nv_bfloat16 g_g1b[MM*64*384];
__device__ __half g_xt16[(long)MM*NN*DD];          // fp16 xt (edge phase only)
__device__ float g_agg [MM*NN*DD];   // fp32 temp (usergemm out)
__device__ float g_xh  [MM*NN*DX];
__device__ float g_reps[MM*NN*DX];
__device__ float g_w   [EE];         // logits in CSR position order
__device__ float g_deg [NN];
__device__ float g_dinv[NN];
__device__ int   g_degD[NN];
__device__ int   g_off [NN+1];
__device__ int   g_cur [NN];
__device__ int   g_srcs[EE];         // src node per CSR position
__device__ int   g_dsts[EE];         // dst node per CSR position
__device__ float g_kmod[MM*DX];
__device__ float g_kp  [MM*DX];
__device__ float g_vp  [MM*DX];

__device__ __forceinline__ float lrelu(float x){ return x > 0.f ? x : 0.01f*x; }
__device__ __forceinline__ float wsum(float v){
  #pragma unroll
  for (int o = 16; o; o >>= 1) v += __shfl_xor_sync(0xffffffffu, v, o);
  return v;
}
__device__ __forceinline__ float wmaxr(float v){
  #pragma unroll
  for (int o = 16; o; o >>= 1) v = fmaxf(v, __shfl_xor_sync(0xffffffffu, v, o));
  return v;
}
__device__ __forceinline__ __nv_bfloat16 hilo(float v, bool lo){
  __nv_bfloat16 h = __float2bfloat16(v);
  return lo ? __float2bfloat16(v - __bfloat162float(h)) : h;
}
__device__ __forceinline__ void put4(__nv_bfloat16* dst, float4 v, float rn){
  float a0=v.x*rn, a1=v.y*rn, a2=v.z*rn, a3=v.w*rn;
  __nv_bfloat16 h[4] = {__float2bfloat16(a0),__float2bfloat16(a1),
                        __float2bfloat16(a2),__float2bfloat16(a3)};
  __nv_bfloat16 l[4] = {
    __float2bfloat16(a0-__bfloat162float(h[0])), __float2bfloat16(a1-__bfloat162float(h[1])),
    __float2bfloat16(a2-__bfloat162float(h[2])), __float2bfloat16(a3-__bfloat162float(h[3]))};
  *(uint2*)dst = *(uint2*)h;
  *(uint2*)(dst+128) = *(uint2*)l;
}

// ---------------- MMA + cp.async primitives ----------------
__device__ __forceinline__ void mma16816(float* d, const uint32_t* a, const uint32_t* b){
  asm volatile("mma.sync.aligned.m16n8k16.row.col.f32.bf16.bf16.f32 "
    "{%0,%1,%2,%3}, {%4,%5,%6,%7}, {%8,%9}, {%0,%1,%2,%3};"
    : "+f"(d[0]), "+f"(d[1]), "+f"(d[2]), "+f"(d[3])
    : "r"(a[0]), "r"(a[1]), "r"(a[2]), "r"(a[3]), "r"(b[0]), "r"(b[1]));
}
__device__ __forceinline__ uint32_t smem_u32(const void* p){
  uint32_t a;
  asm("{ .reg .u64 t; cvta.to.shared.u64 t, %1; cvt.u32.u64 %0, t; }" : "=r"(a) : "l"(p));
  return a;
}
__device__ __forceinline__ void cpasync16(uint32_t sdst, const void* gsrc, bool pred){
  int sz = pred ? 16 : 0;
  asm volatile("cp.async.cg.shared.global [%0], [%1], 16, %2;"
               :: "r"(sdst), "l"(gsrc), "r"(sz));
}
#define CP_COMMIT() asm volatile("cp.async.commit_group;" ::: "memory")
#define CP_WAIT1()  asm volatile("cp.async.wait_group 1;" ::: "memory")
#define CP_WAIT0()  asm volatile("cp.async.wait_group 0;" ::: "memory")

// ---- bf16 HMMA GEMM, K_eff=384 (=3-term split), cp.async double-buffered ---
// A: [M,256] hi|lo.  Bw: [BN,384] = [Bh|Bl|Bh].
// EPI 0: none->fp32 | 1: tanh(+bias)->fp32 | 2: lrelu(+bias)+add->fp32
// EPI 3: lrelu(+bias+add)->fp32 | 5: none->fp16 ONLY (C16)
template<int BN, int EPI>
__global__ void __launch_bounds__(256,2) k_bgemm(
    const __nv_bfloat16* __restrict__ A, const __nv_bfloat16* __restrict__ Bw,
    float* __restrict__ C, __half* __restrict__ C16, int M,
    long sA, long sB, long sC,
    const float* __restrict__ bias, long sBias,
    const float* __restrict__ add, long sAdd)
{
  constexpr int P = 72;
  constexpr int ASZ = 128*P, BSZ = BN*P, STG = ASZ + BSZ;
  constexpr int NF = BN/16;
  constexpr int LB = BN/32;
  extern __shared__ __nv_bfloat16 sm[];
  int z = blockIdx.z;
  A += (long)z*sA; Bw += (long)z*sB;
  if (EPI != 5) C   += (long)z*sC;
  if (EPI == 5) C16 += (long)z*sC;
  if (EPI == 1 || EPI == 2 || EPI == 3) bias += (long)z*sBias;
  if (EPI == 2 || EPI == 3)             add  += (long)z*sAdd;
  int m0 = blockIdx.x*128;
  int tid = threadIdx.x, lane = tid & 31, wid = tid >> 5;
  uint32_t smb = smem_u32(sm);

  auto aload = [&](int t, int buf){
    int cb = ((t & 4) << 5) | ((t & 1) << 6);   // {0,64,0,64,128,192}
    #pragma unroll
    for (int i = 0; i < 4; i++){
      int idx = tid + i*256;
      int r = idx >> 3, c8 = (idx & 7)*8;
      bool inb = (m0 + r) < M;
      const __nv_bfloat16* gp = A + (inb ? ((long)(m0+r)*256 + cb + c8) : 0);
      cpasync16(smb + (uint32_t)(buf*STG + r*P + c8)*2, gp, inb);
    }
    #pragma unroll
    for (int i = 0; i < LB; i++){
      int idx = tid + i*256;
      int r = idx >> 3, c8 = (idx & 7)*8;
      cpasync16(smb + (uint32_t)(buf*STG + ASZ + r*P + c8)*2,
                Bw + (long)r*384 + t*64 + c8, true);
    }
  };

  aload(0, 0);
  CP_COMMIT();

  int wm = (wid & 3) << 5;
  int wn = (wid >> 2) * (BN/2);
  int lr = lane >> 2, lc = (lane & 3) << 1;
  float acc[2][NF][4];
  #pragma unroll
  for (int i = 0; i < 2; i++)
    #pragma unroll
    for (int j = 0; j < NF; j++)
      #pragma unroll
      for (int q = 0; q < 4; q++) acc[i][j][q] = 0.f;

  #pragma unroll
  for (int t = 0; t < 6; t++){
    if (t < 5){ aload(t+1, (t+1)&1); CP_COMMIT(); CP_WAIT1(); }
    else      { CP_WAIT0(); }
    __syncthreads();
    const __nv_bfloat16* As = sm + (t&1)*STG;
    const __nv_bfloat16* Bs = As + ASZ;
    #pragma unroll
    for (int k0 = 0; k0 < 64; k0 += 16){
      int kk = k0 + lc;
      uint32_t a[2][4];
      #pragma unroll
      for (int mi = 0; mi < 2; mi++){
        int r = wm + mi*16 + lr;
        a[mi][0] = *(const uint32_t*)(As + r*P + kk);
        a[mi][1] = *(const uint32_t*)(As + (r+8)*P + kk);
        a[mi][2] = *(const uint32_t*)(As + r*P + kk + 8);
        a[mi][3] = *(const uint32_t*)(As + (r+8)*P + kk + 8);
      }
      #pragma unroll
      for (int nf = 0; nf < NF; nf++){
        int n = wn + nf*8 + lr;
        uint32_t b[2];
        b[0] = *(const uint32_t*)(Bs + n*P + kk);
        b[1] = *(const uint32_t*)(Bs + n*P + kk + 8);
        mma16816(acc[0][nf], a[0], b);
        mma16816(acc[1][nf], a[1], b);
      }
    }
    __syncthreads();
  }

  #pragma unroll
  for (int mi = 0; mi < 2; mi++){
    #pragma unroll
    for (int h = 0; h < 2; h++){
      int row = m0 + wm + mi*16 + lr + h*8;
      if (row >= M) continue;
      #pragma unroll
      for (int nf = 0; nf < NF; nf++){
        int n = wn + nf*8 + lc;
        float x0 = acc[mi][nf][h*2+0];
        float x1 = acc[mi][nf][h*2+1];
        if (EPI == 1){ x0 = tanhf(x0 + bias[n]); x1 = tanhf(x1 + bias[n+1]); }
        else if (EPI == 2){
          x0 = lrelu(x0 + bias[n])   + add[(long)row*BN + n];
          x1 = lrelu(x1 + bias[n+1]) + add[(long)row*BN + n+1];
        } else if (EPI == 3){
          x0 = lrelu(x0 + bias[n]   + add[(long)row*BN + n]);
          x1 = lrelu(x1 + bias[n+1] + add[(long)row*BN + n+1]);
        }
        if (EPI == 5)
          *(__half2*)(C16 + (long)row*BN + n) = __float22half2_rn(make_float2(x0, x1));
        else
          *(float2*)(C + (long)row*BN + n) = make_float2(x0, x1);
      }
    }
  }
}

// ------- k_prep: items normalize->bf16 planes + all input conversions -------
#define CV0 (N_USER*256)
#define WU  (MM*128*384)
#define WL  (MM*64*384)
#define CV1 (CV0 + WU)
#define CV2 (CV1 + WU)
#define CV3 (CV2 + WL)
#define CV4 (CV3 + WL)
__global__ void k_prep(const float* __restrict__ feats, const float* __restrict__ uf,
                       const float* __restrict__ userW, const float* __restrict__ convW,
                       const float* __restrict__ lin1W, const float* __restrict__ g1W){
  long g = (long)blockIdx.x*256 + threadIdx.x;
  if (g < NN){ g_deg[g] = 0.f; g_degD[g] = 0; }
  long w = g >> 5; int lane = (int)(g & 31);
  if (w < (long)MM*N_ITEM){
    int m = (int)(w / N_ITEM), i = (int)(w - (long)m*N_ITEM);
    const float* in = feats + ((long)m*N_ITEM + i)*DD;
    float4 v = *(const float4*)(in + lane*4);
    float ss = wsum(v.x*v.x + v.y*v.y + v.z*v.z + v.w*v.w);
    float rn = 1.f / fmaxf(sqrtf(ss), 1e-12f);
    put4(g_xb + ((long)m*NN + i)*256 + lane*4, v, rn);
  }
  if (g < CV0){
    int r = (int)(g >> 8), c = (int)(g & 255);
    g_ufb[g] = hilo(uf[r*128 + (c & 127)], c >= 128);
  } else if (g < CV1){
    long j = g - CV0;
    int m = (int)(j/49152); int r2 = (int)(j%49152);
    int n = r2/384, kp = r2%384, sel = kp>>7, kk = kp&127;
    g_uwb[j] = hilo(userW[(long)m*16384 + n*128 + kk], sel == 1);
  } else if (g < CV2){
    long j = g - CV1;
    int m = (int)(j/49152); int r2 = (int)(j%49152);
    int n = r2/384, kp = r2%384, sel = kp>>7, kk = kp&127;
    g_cwb[j] = hilo(convW[(long)m*16384 + kk*128 + n], sel == 1);
  } else if (g < CV3){
    long j = g - CV2;
    int m = (int)(j/24576); int r2 = (int)(j%24576);
    int n = r2/384, kp = r2%384, sel = kp>>7, kk = kp&127;
    g_l1b[j] = hilo(lin1W[(long)m*8192 + n*128 + kk], sel == 1);
  } else if (g < CV4){
    long j = g - CV3;
    int m = (int)(j/24576); int r2 = (int)(j%24576);
    int n = r2/384, kp = r2%384, sel = kp>>7, kk = kp&127;
    g_g1b[j] = hilo(g1W[(long)m*8192 + n*128 + kk], sel == 1);
  }
}
__global__ void k_norm_users(){
  int g = blockIdx.x*256 + threadIdx.x;
  int w = g >> 5, lane = g & 31;
  if (w >= MM*N_USER) return;
  int m = w / N_USER, i = w - m*N_USER;
  const float* in = g_agg + ((long)m*N_USER + i)*DD;
  float4 v = *(const float4*)(in + lane*4);
  float ss = wsum(v.x*v.x + v.y*v.y + v.z*v.z + v.w*v.w);
  float rn = 1.f / fmaxf(sqrtf(ss), 1e-12f);
  put4(g_xb + ((long)m*NN + N_ITEM + i)*256 + lane*4, v, rn);
}

// ---------------- CSR build ----------------
__global__ void k_deg(const int* __restrict__ src, const int* __restrict__ dst){
  int e = blockIdx.x*256 + threadIdx.x;
  if (e < EE){ atomicAdd(&g_deg[src[e]], 1.f); atomicAdd(&g_degD[dst[e]], 1); }
}
#define SCAN_T 1024
__global__ void __launch_bounds__(SCAN_T) k_scan(){
  __shared__ int ps[SCAN_T];
  int t = threadIdx.x;
  const int C = (NN + SCAN_T - 1)/SCAN_T;
  int lo = t*C, hi = lo+C < NN ? lo+C : NN;
  int s = 0;
  for (int i = lo; i < hi; i++){
    s += g_degD[i];
    float d = g_deg[i];
    g_dinv[i] = d > 0.f ? 1.f/sqrtf(d) : 0.f;
  }
  ps[t] = s; __syncthreads();
  for (int off = 1; off < SCAN_T; off <<= 1){
    int v = (t >= off) ? ps[t-off] : 0;
    __syncthreads();
    ps[t] += v;
    __syncthreads();
  }
  int run = t ? ps[t-1] : 0;
  for (int i = lo; i < hi; i++){ int d = g_degD[i]; g_off[i] = run; g_cur[i] = run; run += d; }
  if (t == SCAN_T-1) g_off[NN] = run;
}
__global__ void k_scatter(const int* __restrict__ src, const int* __restrict__ dst){
  int e = blockIdx.x*256 + threadIdx.x;
  if (e < EE){
    int d = dst[e];
    int p = atomicAdd(&g_cur[d], 1);
    g_srcs[p] = src[e];
    g_dsts[p] = d;
  }
}

// ------- edge logits (CSR order, fp16 rows): 8 lanes/edge, 4 edges/warp -----
__global__ void __launch_bounds__(256) k_ipwm(const __half* __restrict__ xt16){
  int gw = (blockIdx.x << 3) | (threadIdx.x >> 5);
  int lane = threadIdx.x & 31;
  int sub = lane >> 3, l8 = lane & 7;
  int i = (gw << 2) | sub;
  if (i >= EE) return;
  int s = g_srcs[i], d = g_dsts[i];
  const __half* ps = xt16 + (long)s*DD;
  const __half* pd = xt16 + (long)d*DD;
  float acc = 0.f;
  #pragma unroll
  for (int c = 0; c < 2; c++){
    uint4 a4 = *(const uint4*)(ps + c*64 + l8*8);
    uint4 b4 = *(const uint4*)(pd + c*64 + l8*8);
    const __half2* ah = (const __half2*)&a4;
    const __half2* bh = (const __half2*)&b4;
    #pragma unroll
    for (int j = 0; j < 4; j++){
      float2 a = __half22float2(ah[j]);
      float2 b = __half22float2(bh[j]);
      acc += b.x*lrelu(a.x) + b.y*lrelu(a.y);
    }
  }
  #pragma unroll
  for (int o = 4; o; o >>= 1) acc += __shfl_xor_sync(0xffffffffu, acc, o);
  if (l8 == 0){
    float di = g_dinv[s];
    g_w[i] = acc / (1.f + expf(-di*acc));
  }
}

// fused per-dst segment softmax + fp16 aggregate + bias + l2norm + lrelu -> bf16 h
__global__ void __launch_bounds__(256) k_nodeagg(const __half* __restrict__ xt16,
                                                 const float* __restrict__ cb,
                                                 __nv_bfloat16* __restrict__ hb){
  int g = blockIdx.x*256 + threadIdx.x;
  int n = g >> 5, lane = g & 31;
  if (n >= NN) return;
  int o0 = g_off[n], o1 = g_off[n+1];
  float wm = -3.4e38f;
  for (int i = o0 + lane; i < o1; i += 32) wm = fmaxf(wm, g_w[i]);
  wm = wmaxr(wm);
  float es = 0.f;
  for (int i = o0 + lane; i < o1; i += 32) es += expf(g_w[i] - wm);
  es = wsum(es);
  float rs = 1.f / (es + 1e-16f);
  float4 acc = make_float4(0,0,0,0);
  for (int i = o0; i < o1; i++){
    float att = expf(g_w[i] - wm) * rs;
    uint2 av = *(const uint2*)(xt16 + (long)g_srcs[i]*DD + lane*4);
    float2 a0 = __half22float2(*(__half2*)&av.x);
    float2 a1 = __half22float2(*(__half2*)&av.y);
    acc.x += att*a0.x; acc.y += att*a0.y; acc.z += att*a1.x; acc.w += att*a1.y;
  }
  float4 b4 = *(const float4*)(cb + lane*4);
  acc.x += b4.x; acc.y += b4.y; acc.z += b4.z; acc.w += b4.w;
  float ss = acc.x*acc.x + acc.y*acc.y + acc.z*acc.z + acc.w*acc.w;
  ss = wsum(ss);
  float rn = 1.f / fmaxf(sqrtf(ss), 1e-12f);
  float4 o;
  o.x = lrelu(acc.x*rn); o.y = lrelu(acc.y*rn);
  o.z = lrelu(acc.z*rn); o.w = lrelu(acc.w*rn);
  put4(hb + (long)n*256 + lane*4, o, 1.f);
}

// ---------------- tail ----------------
__global__ void k_mean(float* __restrict__ out_rep){
  int i = blockIdx.x*256 + threadIdx.x;
  if (i < MM*DX) g_kmod[i] = 0.f;
  if (i < NN*DX)
    out_rep[i] = 0.25f * (g_reps[i] + g_reps[(long)NN*DX + i]
                        + g_reps[2L*NN*DX + i] + g_reps[3L*NN*DX + i]);
}
__global__ void __launch_bounds__(64) k_kmod(const int* __restrict__ pi){
  int m = blockIdx.y, j = threadIdx.x;
  int b0 = blockIdx.x * 64;
  float acc = 0.f;
  #pragma unroll 4
  for (int t = 0; t < 64; t++){
    int p = pi[b0 + t];
    acc += g_reps[((long)m*NN + p)*DX + j];
  }
  atomicAdd(&g_kmod[m*DX + j], acc);
}
__global__ void k_kpvp(const float* __restrict__ kW, const float* __restrict__ vW){
  int tid = threadIdx.x;
  int m = tid >> 6, j = tid & 63;
  float s1 = 0.f, s2 = 0.f;
  #pragma unroll 8
  for (int k = 0; k < DX; k++){
    float km = g_kmod[m*DX + k] * (1.f/BB);
    s1 += km * kW[j*DX + k];
    s2 += km * vW[j*DX + k];
  }
  g_kp[m*DX + j] = s1;
  g_vp[m*DX + j] = s2;
}
__global__ void __launch_bounds__(64) k_final(
    const float* __restrict__ rep,
    const int* __restrict__ un, const int* __restrict__ pi, const int* __restrict__ ni,
    const float* __restrict__ qW,
    const float* __restrict__ mpW1, const float* __restrict__ mpb1,
    const float* __restrict__ mpW2, const float* __restrict__ mpb2,
    float* __restrict__ out_pos, float* __restrict__ out_neg, float* __restrict__ out_pred)
{
  int b = blockIdx.x, j = threadIdx.x;
  __shared__ float su[DX], sq[DX], sa[DX], sp[DX], sn[DX], sc[MM], red[DX];
  su[j] = rep[(long)un[b]*DX + j];
  sp[j] = rep[(long)pi[b]*DX + j];
  sn[j] = rep[(long)ni[b]*DX + j];
  __syncthreads();
  float q = 0.f;
  #pragma unroll 8
  for (int k = 0; k < DX; k++) q += su[k] * qW[j*DX + k];
  sq[j] = q;
  __syncthreads();
  if (j < MM){
    float s = 0.f;
    #pragma unroll 8
    for (int k = 0; k < DX; k++) s += sq[k] * g_kp[j*DX + k];
    sc[j] = s * 0.125f;
  }
  __syncthreads();
  float mx = fmaxf(fmaxf(sc[0], sc[1]), fmaxf(sc[2], sc[3]));
  float e0 = expf(sc[0]-mx), e1 = expf(sc[1]-mx), e2 = expf(sc[2]-mx), e3 = expf(sc[3]-mx);
  float es = e0 + e1 + e2 + e3;
  float av = (e0*g_vp[0*DX+j] + e1*g_vp[1*DX+j] + e2*g_vp[2*DX+j] + e3*g_vp[3*DX+j]) / es;
  sa[j] = av;
  red[j] = av * sp[j];
  __syncthreads();
  for (int s = 32; s > 0; s >>= 1){ if (j < s) red[j] += red[j+s]; __syncthreads(); }
  if (j == 0) out_pos[b] = red[0];
  __syncthreads();
  red[j] = av * sn[j];
  __syncthreads();
  for (int s = 32; s > 0; s >>= 1){ if (j < s) red[j] += red[j+s]; __syncthreads(); }
  if (j == 0) out_neg[b] = red[0];
  __syncthreads();
  float h = mpb1[j];
  #pragma unroll 8
  for (int k = 0; k < DX; k++) h += sa[k] * mpW1[j*2*DX + k];
  #pragma unroll 8
  for (int k = 0; k < DX; k++) h += sp[k] * mpW1[j*2*DX + DX + k];
  h = lrelu(h);
  red[j] = h * mpW2[j];
  __syncthreads();
  for (int s = 32; s > 0; s >>= 1){ if (j < s) red[j] += red[j+s]; __syncthreads(); }
  if (j == 0) out_pred[b] = red[0] + mpb2[0];
}

// ---------------- host ----------------
extern "C" void kernel_launch(void* const* d_in, const int* in_sizes, int n_in,
                              void* d_out, int out_size)
{
  const float* feats  = (const float*)d_in[0];
  const float* uf     = (const float*)d_in[1];
  const float* userW  = (const float*)d_in[2];
  const float* userb  = (const float*)d_in[3];
  const float* convW  = (const float*)d_in[4];
  const float* convb  = (const float*)d_in[5];
  const float* lin1W  = (const float*)d_in[6];
  const float* lin1b  = (const float*)d_in[7];
  const float* g1W    = (const float*)d_in[8];
  const float* g1b    = (const float*)d_in[9];
  const float* id_emb = (const float*)d_in[10];
  const float* qW     = (const float*)d_in[11];
  const float* kW     = (const float*)d_in[12];
  const float* vW     = (const float*)d_in[13];
  const float* mpW1   = (const float*)d_in[14];
  const float* mpb1   = (const float*)d_in[15];
  const float* mpW2   = (const float*)d_in[16];
  const float* mpb2   = (const float*)d_in[17];
  const int*   eidx   = (const int*)d_in[18];
  const int*   un     = (const int*)d_in[19];
  const int*   pi     = (const int*)d_in[20];
  const int*   ni     = (const int*)d_in[21];
  const int *src = eidx, *dst = eidx + EE;

  float* out      = (float*)d_out;
  float* out_pos  = out;
  float* out_neg  = out + BB;
  float* out_rep  = out + 2*BB;
  float* out_pred = out + 2*BB + (long)NN*DX;

  void* p;
  cudaGetSymbolAddress(&p, g_xb);   __nv_bfloat16* xb  = (__nv_bfloat16*)p;
  cudaGetSymbolAddress(&p, g_hb);   __nv_bfloat16* hb  = (__nv_bfloat16*)p;
  cudaGetSymbolAddress(&p, g_ufb);  __nv_bfloat16* ufb = (__nv_bfloat16*)p;
  cudaGetSymbolAddress(&p, g_uwb);  __nv_bfloat16* uwb = (__nv_bfloat16*)p;
  cudaGetSymbolAddress(&p, g_cwb);  __nv_bfloat16* cwb = (__nv_bfloat16*)p;
  cudaGetSymbolAddress(&p, g_l1b);  __nv_bfloat16* l1b = (__nv_bfloat16*)p;
  cudaGetSymbolAddress(&p, g_g1b);  __nv_bfloat16* g1bw= (__nv_bfloat16*)p;
  cudaGetSymbolAddress(&p, g_xt16); __half* xt16 = (__half*)p;
  cudaGetSymbolAddress(&p, g_agg);  float* agg   = (float*)p;
  cudaGetSymbolAddress(&p, g_xh);   float* xh    = (float*)p;
  cudaGetSymbolAddress(&p, g_reps); float* reps  = (float*)p;

  const int SMB128 = (128*72 + 128*72)*2*2;   // 73728 B
  const int SMB64  = (128*72 + 64*72)*2*2;    // 55296 B
  cudaFuncSetAttribute(k_bgemm<128,1>, cudaFuncAttributeMaxDynamicSharedMemorySize, SMB128);
  cudaFuncSetAttribute(k_bgemm<128,5>, cudaFuncAttributeMaxDynamicSharedMemorySize, SMB128);
  cudaFuncSetAttribute(k_bgemm<64,2>,  cudaFuncAttributeMaxDynamicSharedMemorySize, SMB64);
  cudaFuncSetAttribute(k_bgemm<64,3>,  cudaFuncAttributeMaxDynamicSharedMemorySize, SMB64);

  // (1) prep
  k_prep<<<(MM*N_ITEM*32)/256, 256>>>(feats, uf, userW, convW, lin1W, g1W);
  // (2) user transform (batched over m)
  {
    dim3 g((N_USER+127)/128, 1, MM);
    k_bgemm<128,1><<<g, 256, SMB128>>>(ufb, uwb, agg, nullptr, N_USER,
                                       0, 128L*384, (long)N_USER*DD, userb, DD, nullptr, 0);
  }
  // (3) users normalize -> bf16 planes
  k_norm_users<<<(MM*N_USER*32 + 255)/256, 256>>>();
  // (4) xt16 = x @ convW (fp16-only out, batched)  <-- ncu profile slot
  {
    dim3 g((NN+127)/128, 1, MM);
    k_bgemm<128,5><<<g, 256, SMB128>>>(xb, cwb, nullptr, xt16, NN,
                                       (long)NN*256, 128L*384, (long)NN*DD,
                                       nullptr, 0, nullptr, 0);
  }
  // (5) xh = lrelu(x @ lin1W^T + b) + id_emb (batched)
  {
    dim3 g((NN+127)/128, 1, MM);
    k_bgemm<64,2><<<g, 256, SMB64>>>(xb, l1b, xh, nullptr, NN,
                                     (long)NN*256, 64L*384, (long)NN*DX,
                                     lin1b, DX, id_emb, 0);
  }
  // CSR build (once)
  k_deg    <<<(EE+255)/256, 256>>>(src, dst);
  k_scan   <<<1, SCAN_T>>>();
  k_scatter<<<(EE+255)/256, 256>>>(src, dst);

  // edge pipeline per modality (fp16 xt slice hot in L2)
  for (int m = 0; m < MM; m++){
    const __half* xt16m = xt16 + (long)m*NN*DD;
    k_ipwm   <<<(EE*8 + 255)/256, 256>>>(xt16m);
    k_nodeagg<<<(NN*32 + 255)/256, 256>>>(xt16m, convb + m*DD, hb + (long)m*NN*256);
  }

  // reps = lrelu(h @ g1W^T + g1b + xh) (batched)
  {
    dim3 g((NN+127)/128, 1, MM);
    k_bgemm<64,3><<<g, 256, SMB64>>>(hb, g1bw, reps, nullptr, NN,
                                     (long)NN*256, 64L*384, (long)NN*DX,
                                     g1b, DX, xh, (long)NN*DX);
  }

  k_mean<<<(NN*DX + 255)/256, 256>>>(out_rep);
  k_kmod<<<dim3(BB/64, MM), 64>>>(pi);
  k_kpvp<<<1, 256>>>(kW, vW);
  k_final<<<BB, 64>>>(out_rep, un, pi, ni, qW, mpW1, mpb1, mpW2, mpb2,
                      out_pos, out_neg, out_pred);
}

// round 15
// speedup vs baseline: 1.1141x; 1.0105x over previous
#include <cuda_runtime.h>
#include <cuda_bf16.h>
#include <cuda_fp16.h>
#include <cstdint>
#include <math.h>

#define MM 4
#define N_ITEM 40000
#define N_USER 10000
#define NN 50000
#define DD 128
#define DX 64
#define EE 400000
#define BB 4096

// ---------------- scratch (device globals; allocation-free) ----------------
__device__ __nv_bfloat16 g_xb [(long)MM*NN*256];   // x hi|lo planes
__device__ __nv_bfloat16 g_hb [(long)MM*NN*256];   // h hi|lo planes
__device__ __nv_bfloat16 g_ufb[(long)N_USER*256];
__device__ __nv_bfloat16 g_uwb[MM*128*384];
__device__ __nv_bfloat16 g_cwb[MM*128*384];
__device__ __nv_bfloat16 g_l1b[MM*64*384];
__device__ __nv_bfloat16 g_g1b[MM*64*384];
__device__ __half g_xt16[(long)MM*NN*DD];          // fp16 xt (edge phase only)
__device__ float g_agg [MM*NN*DD];   // fp32 temp (usergemm out)
__device__ float g_xh  [MM*NN*DX];
__device__ float g_reps[MM*NN*DX];
__device__ float g_w   [EE];         // logits in CSR position order
__device__ float g_deg [NN];
__device__ float g_dinv[NN];
__device__ int   g_degD[NN];
__device__ int   g_off [NN+1];
__device__ int   g_cur [NN];
__device__ int   g_srcs[EE];
__device__ int   g_dsts[EE];
__device__ float g_kmod[MM*DX];
__device__ float g_kp  [MM*DX];
__device__ float g_vp  [MM*DX];

__device__ __forceinline__ float lrelu(float x){ return x > 0.f ? x : 0.01f*x; }
__device__ __forceinline__ float wsum(float v){
  #pragma unroll
  for (int o = 16; o; o >>= 1) v += __shfl_xor_sync(0xffffffffu, v, o);
  return v;
}
__device__ __forceinline__ float wmaxr(float v){
  #pragma unroll
  for (int o = 16; o; o >>= 1) v = fmaxf(v, __shfl_xor_sync(0xffffffffu, v, o));
  return v;
}
__device__ __forceinline__ __nv_bfloat16 hilo(float v, bool lo){
  __nv_bfloat16 h = __float2bfloat16(v);
  return lo ? __float2bfloat16(v - __bfloat162float(h)) : h;
}
__device__ __forceinline__ void put4(__nv_bfloat16* dst, float4 v, float rn){
  float a0=v.x*rn, a1=v.y*rn, a2=v.z*rn, a3=v.w*rn;
  __nv_bfloat16 h[4] = {__float2bfloat16(a0),__float2bfloat16(a1),
                        __float2bfloat16(a2),__float2bfloat16(a3)};
  __nv_bfloat16 l[4] = {
    __float2bfloat16(a0-__bfloat162float(h[0])), __float2bfloat16(a1-__bfloat162float(h[1])),
    __float2bfloat16(a2-__bfloat162float(h[2])), __float2bfloat16(a3-__bfloat162float(h[3]))};
  *(uint2*)dst = *(uint2*)h;
  *(uint2*)(dst+128) = *(uint2*)l;
}

// ---------------- MMA + cp.async + ldmatrix primitives ----------------
__device__ __forceinline__ void mma16816(float* d, const uint32_t* a, const uint32_t* b){
  asm volatile("mma.sync.aligned.m16n8k16.row.col.f32.bf16.bf16.f32 "
    "{%0,%1,%2,%3}, {%4,%5,%6,%7}, {%8,%9}, {%0,%1,%2,%3};"
    : "+f"(d[0]), "+f"(d[1]), "+f"(d[2]), "+f"(d[3])
    : "r"(a[0]), "r"(a[1]), "r"(a[2]), "r"(a[3]), "r"(b[0]), "r"(b[1]));
}
__device__ __forceinline__ uint32_t smem_u32(const void* p){
  uint32_t a;
  asm("{ .reg .u64 t; cvta.to.shared.u64 t, %1; cvt.u32.u64 %0, t; }" : "=r"(a) : "l"(p));
  return a;
}
__device__ __forceinline__ void cpasync16(uint32_t sdst, const void* gsrc, bool pred){
  int sz = pred ? 16 : 0;
  asm volatile("cp.async.cg.shared.global [%0], [%1], 16, %2;"
               :: "r"(sdst), "l"(gsrc), "r"(sz));
}
#define CP_COMMIT() asm volatile("cp.async.commit_group;" ::: "memory")
#define CP_WAIT1()  asm volatile("cp.async.wait_group 1;" ::: "memory")
#define CP_WAIT0()  asm volatile("cp.async.wait_group 0;" ::: "memory")
#define LDSM4(r0,r1,r2,r3,addr) \
  asm volatile("ldmatrix.sync.aligned.m8n8.x4.shared.b16 {%0,%1,%2,%3}, [%4];" \
    : "=r"(r0),"=r"(r1),"=r"(r2),"=r"(r3) : "r"(addr))

// ---- bf16 HMMA GEMM, K_eff=384, cp.async double-buffered, ldmatrix frags ---
// A: [M,256] hi|lo.  Bw: [BN,384] = [Bh|Bl|Bh].
// EPI 0: none->fp32 | 1: tanh(+bias)->fp32 | 2: lrelu(+bias)+add->fp32
// EPI 3: lrelu(+bias+add)->fp32 | 5: none->fp16 ONLY (C16)
template<int BN, int EPI>
__global__ void __launch_bounds__(256,2) k_bgemm(
    const __nv_bfloat16* __restrict__ A, const __nv_bfloat16* __restrict__ Bw,
    float* __restrict__ C, __half* __restrict__ C16, int M,
    long sA, long sB, long sC,
    const float* __restrict__ bias, long sBias,
    const float* __restrict__ add, long sAdd)
{
  constexpr int P = 72;
  constexpr int ASZ = 128*P, BSZ = BN*P, STG = ASZ + BSZ;
  constexpr int NF = BN/16;
  constexpr int LB = BN/32;
  extern __shared__ __nv_bfloat16 sm[];
  int z = blockIdx.z;
  A += (long)z*sA; Bw += (long)z*sB;
  if (EPI != 5) C   += (long)z*sC;
  if (EPI == 5) C16 += (long)z*sC;
  if (EPI == 1 || EPI == 2 || EPI == 3) bias += (long)z*sBias;
  if (EPI == 2 || EPI == 3)             add  += (long)z*sAdd;
  int m0 = blockIdx.x*128;
  int tid = threadIdx.x, lane = tid & 31, wid = tid >> 5;
  uint32_t smb = smem_u32(sm);

  auto aload = [&](int t, int buf){
    int cb = ((t & 4) << 5) | ((t & 1) << 6);   // {0,64,0,64,128,192}
    #pragma unroll
    for (int i = 0; i < 4; i++){
      int idx = tid + i*256;
      int r = idx >> 3, c8 = (idx & 7)*8;
      bool inb = (m0 + r) < M;
      const __nv_bfloat16* gp = A + (inb ? ((long)(m0+r)*256 + cb + c8) : 0);
      cpasync16(smb + (uint32_t)(buf*STG + r*P + c8)*2, gp, inb);
    }
    #pragma unroll
    for (int i = 0; i < LB; i++){
      int idx = tid + i*256;
      int r = idx >> 3, c8 = (idx & 7)*8;
      cpasync16(smb + (uint32_t)(buf*STG + ASZ + r*P + c8)*2,
                Bw + (long)r*384 + t*64 + c8, true);
    }
  };

  aload(0, 0);
  CP_COMMIT();

  int wm = (wid & 3) << 5;
  int wn = (wid >> 2) * (BN/2);
  int lr = lane >> 2, lc = (lane & 3) << 1;
  int grp = lane >> 3, r8 = lane & 7;
  // ldmatrix per-lane element offsets (halves)
  uint32_t offA[2], offB[NF/2];
  #pragma unroll
  for (int mi = 0; mi < 2; mi++)
    offA[mi] = (uint32_t)((wm + mi*16 + (grp & 1)*8 + r8)*P + (grp >> 1)*8);
  #pragma unroll
  for (int pp = 0; pp < NF/2; pp++)
    offB[pp] = (uint32_t)(ASZ + (wn + pp*16 + (grp >> 1)*8 + r8)*P + (grp & 1)*8);

  float acc[2][NF][4];
  #pragma unroll
  for (int i = 0; i < 2; i++)
    #pragma unroll
    for (int j = 0; j < NF; j++)
      #pragma unroll
      for (int q = 0; q < 4; q++) acc[i][j][q] = 0.f;

  #pragma unroll
  for (int t = 0; t < 6; t++){
    if (t < 5){ aload(t+1, (t+1)&1); CP_COMMIT(); CP_WAIT1(); }
    else      { CP_WAIT0(); }
    __syncthreads();
    uint32_t tb = smb + (uint32_t)((t&1)*STG)*2;
    #pragma unroll
    for (int k0 = 0; k0 < 64; k0 += 16){
      uint32_t a[2][4];
      #pragma unroll
      for (int mi = 0; mi < 2; mi++)
        LDSM4(a[mi][0], a[mi][1], a[mi][2], a[mi][3], tb + (offA[mi] + k0)*2);
      uint32_t b[NF][2];
      #pragma unroll
      for (int pp = 0; pp < NF/2; pp++)
        LDSM4(b[2*pp][0], b[2*pp][1], b[2*pp+1][0], b[2*pp+1][1], tb + (offB[pp] + k0)*2);
      #pragma unroll
      for (int nf = 0; nf < NF; nf++){
        mma16816(acc[0][nf], a[0], b[nf]);
        mma16816(acc[1][nf], a[1], b[nf]);
      }
    }
    __syncthreads();
  }

  #pragma unroll
  for (int mi = 0; mi < 2; mi++){
    #pragma unroll
    for (int h = 0; h < 2; h++){
      int row = m0 + wm + mi*16 + lr + h*8;
      if (row >= M) continue;
      #pragma unroll
      for (int nf = 0; nf < NF; nf++){
        int n = wn + nf*8 + lc;
        float x0 = acc[mi][nf][h*2+0];
        float x1 = acc[mi][nf][h*2+1];
        if (EPI == 1){ x0 = tanhf(x0 + bias[n]); x1 = tanhf(x1 + bias[n+1]); }
        else if (EPI == 2){
          x0 = lrelu(x0 + bias[n])   + add[(long)row*BN + n];
          x1 = lrelu(x1 + bias[n+1]) + add[(long)row*BN + n+1];
        } else if (EPI == 3){
          x0 = lrelu(x0 + bias[n]   + add[(long)row*BN + n]);
          x1 = lrelu(x1 + bias[n+1] + add[(long)row*BN + n+1]);
        }
        if (EPI == 5)
          *(__half2*)(C16 + (long)row*BN + n) = __float22half2_rn(make_float2(x0, x1));
        else
          *(float2*)(C + (long)row*BN + n) = make_float2(x0, x1);
      }
    }
  }
}

// ------- k_prep: items normalize->bf16 planes + all input conversions -------
#define CV0 (N_USER*256)
#define WU  (MM*128*384)
#define WL  (MM*64*384)
#define CV1 (CV0 + WU)
#define CV2 (CV1 + WU)
#define CV3 (CV2 + WL)
#define CV4 (CV3 + WL)
__global__ void k_prep(const float* __restrict__ feats, const float* __restrict__ uf,
                       const float* __restrict__ userW, const float* __restrict__ convW,
                       const float* __restrict__ lin1W, const float* __restrict__ g1W){
  long g = (long)blockIdx.x*256 + threadIdx.x;
  if (g < NN){ g_deg[g] = 0.f; g_degD[g] = 0; }
  long w = g >> 5; int lane = (int)(g & 31);
  if (w < (long)MM*N_ITEM){
    int m = (int)(w / N_ITEM), i = (int)(w - (long)m*N_ITEM);
    const float* in = feats + ((long)m*N_ITEM + i)*DD;
    float4 v = *(const float4*)(in + lane*4);
    float ss = wsum(v.x*v.x + v.y*v.y + v.z*v.z + v.w*v.w);
    float rn = 1.f / fmaxf(sqrtf(ss), 1e-12f);
    put4(g_xb + ((long)m*NN + i)*256 + lane*4, v, rn);
  }
  if (g < CV0){
    int r = (int)(g >> 8), c = (int)(g & 255);
    g_ufb[g] = hilo(uf[r*128 + (c & 127)], c >= 128);
  } else if (g < CV1){
    long j = g - CV0;
    int m = (int)(j/49152); int r2 = (int)(j%49152);
    int n = r2/384, kp = r2%384, sel = kp>>7, kk = kp&127;
    g_uwb[j] = hilo(userW[(long)m*16384 + n*128 + kk], sel == 1);
  } else if (g < CV2){
    long j = g - CV1;
    int m = (int)(j/49152); int r2 = (int)(j%49152);
    int n = r2/384, kp = r2%384, sel = kp>>7, kk = kp&127;
    g_cwb[j] = hilo(convW[(long)m*16384 + kk*128 + n], sel == 1);
  } else if (g < CV3){
    long j = g - CV2;
    int m = (int)(j/24576); int r2 = (int)(j%24576);
    int n = r2/384, kp = r2%384, sel = kp>>7, kk = kp&127;
    g_l1b[j] = hilo(lin1W[(long)m*8192 + n*128 + kk], sel == 1);
  } else if (g < CV4){
    long j = g - CV3;
    int m = (int)(j/24576); int r2 = (int)(j%24576);
    int n = r2/384, kp = r2%384, sel = kp>>7, kk = kp&127;
    g_g1b[j] = hilo(g1W[(long)m*8192 + n*128 + kk], sel == 1);
  }
}
__global__ void k_norm_users(){
  int g = blockIdx.x*256 + threadIdx.x;
  int w = g >> 5, lane = g & 31;
  if (w >= MM*N_USER) return;
  int m = w / N_USER, i = w - m*N_USER;
  const float* in = g_agg + ((long)m*N_USER + i)*DD;
  float4 v = *(const float4*)(in + lane*4);
  float ss = wsum(v.x*v.x + v.y*v.y + v.z*v.z + v.w*v.w);
  float rn = 1.f / fmaxf(sqrtf(ss), 1e-12f);
  put4(g_xb + ((long)m*NN + N_ITEM + i)*256 + lane*4, v, rn);
}

// ---------------- CSR build ----------------
__global__ void k_deg(const int* __restrict__ src, const int* __restrict__ dst){
  int e = blockIdx.x*256 + threadIdx.x;
  if (e < EE){ atomicAdd(&g_deg[src[e]], 1.f); atomicAdd(&g_degD[dst[e]], 1); }
}
#define SCAN_T 1024
__global__ void __launch_bounds__(SCAN_T) k_scan(){
  __shared__ int ps[SCAN_T];
  int t = threadIdx.x;
  const int C = (NN + SCAN_T - 1)/SCAN_T;
  int lo = t*C, hi = lo+C < NN ? lo+C : NN;
  int s = 0;
  for (int i = lo; i < hi; i++){
    s += g_degD[i];
    float d = g_deg[i];
    g_dinv[i] = d > 0.f ? 1.f/sqrtf(d) : 0.f;
  }
  ps[t] = s; __syncthreads();
  for (int off = 1; off < SCAN_T; off <<= 1){
    int v = (t >= off) ? ps[t-off] : 0;
    __syncthreads();
    ps[t] += v;
    __syncthreads();
  }
  int run = t ? ps[t-1] : 0;
  for (int i = lo; i < hi; i++){ int d = g_degD[i]; g_off[i] = run; g_cur[i] = run; run += d; }
  if (t == SCAN_T-1) g_off[NN] = run;
}
__global__ void k_scatter(const int* __restrict__ src, const int* __restrict__ dst){
  int e = blockIdx.x*256 + threadIdx.x;
  if (e < EE){
    int d = dst[e];
    int p = atomicAdd(&g_cur[d], 1);
    g_srcs[p] = src[e];
    g_dsts[p] = d;
  }
}

// ------- edge logits (CSR order, fp16 rows): 8 lanes/edge, 4 edges/warp -----
__global__ void __launch_bounds__(256) k_ipwm(const __half* __restrict__ xt16){
  int gw = (blockIdx.x << 3) | (threadIdx.x >> 5);
  int lane = threadIdx.x & 31;
  int sub = lane >> 3, l8 = lane & 7;
  int i = (gw << 2) | sub;
  if (i >= EE) return;
  int s = g_srcs[i], d = g_dsts[i];
  const __half* ps = xt16 + (long)s*DD;
  const __half* pd = xt16 + (long)d*DD;
  float acc = 0.f;
  #pragma unroll
  for (int c = 0; c < 2; c++){
    uint4 a4 = *(const uint4*)(ps + c*64 + l8*8);
    uint4 b4 = *(const uint4*)(pd + c*64 + l8*8);
    const __half2* ah = (const __half2*)&a4;
    const __half2* bh = (const __half2*)&b4;
    #pragma unroll
    for (int j = 0; j < 4; j++){
      float2 a = __half22float2(ah[j]);
      float2 b = __half22float2(bh[j]);
      acc += b.x*lrelu(a.x) + b.y*lrelu(a.y);
    }
  }
  #pragma unroll
  for (int o = 4; o; o >>= 1) acc += __shfl_xor_sync(0xffffffffu, acc, o);
  if (l8 == 0){
    float di = g_dinv[s];
    g_w[i] = acc / (1.f + expf(-di*acc));
  }
}

// fused per-dst segment softmax + fp16 aggregate + bias + l2norm + lrelu -> bf16 h
__global__ void __launch_bounds__(256) k_nodeagg(const __half* __restrict__ xt16,
                                                 const float* __restrict__ cb,
                                                 __nv_bfloat16* __restrict__ hb){
  int g = blockIdx.x*256 + threadIdx.x;
  int n = g >> 5, lane = g & 31;
  if (n >= NN) return;
  int o0 = g_off[n], o1 = g_off[n+1];
  float wm = -3.4e38f;
  for (int i = o0 + lane; i < o1; i += 32) wm = fmaxf(wm, g_w[i]);
  wm = wmaxr(wm);
  float es = 0.f;
  for (int i = o0 + lane; i < o1; i += 32) es += expf(g_w[i] - wm);
  es = wsum(es);
  float rs = 1.f / (es + 1e-16f);
  float4 acc = make_float4(0,0,0,0);
  for (int i = o0; i < o1; i++){
    float att = expf(g_w[i] - wm) * rs;
    uint2 av = *(const uint2*)(xt16 + (long)g_srcs[i]*DD + lane*4);
    float2 a0 = __half22float2(*(__half2*)&av.x);
    float2 a1 = __half22float2(*(__half2*)&av.y);
    acc.x += att*a0.x; acc.y += att*a0.y; acc.z += att*a1.x; acc.w += att*a1.y;
  }
  float4 b4 = *(const float4*)(cb + lane*4);
  acc.x += b4.x; acc.y += b4.y; acc.z += b4.z; acc.w += b4.w;
  float ss = acc.x*acc.x + acc.y*acc.y + acc.z*acc.z + acc.w*acc.w;
  ss = wsum(ss);
  float rn = 1.f / fmaxf(sqrtf(ss), 1e-12f);
  float4 o;
  o.x = lrelu(acc.x*rn); o.y = lrelu(acc.y*rn);
  o.z = lrelu(acc.z*rn); o.w = lrelu(acc.w*rn);
  put4(hb + (long)n*256 + lane*4, o, 1.f);
}

// ---------------- tail ----------------
__global__ void k_mean(float* __restrict__ out_rep){
  int i = blockIdx.x*256 + threadIdx.x;
  if (i < MM*DX) g_kmod[i] = 0.f;
  if (i < NN*DX)
    out_rep[i] = 0.25f * (g_reps[i] + g_reps[(long)NN*DX + i]
                        + g_reps[2L*NN*DX + i] + g_reps[3L*NN*DX + i]);
}
__global__ void __launch_bounds__(64) k_kmod(const int* __restrict__ pi){
  int m = blockIdx.y, j = threadIdx.x;
  int b0 = blockIdx.x * 64;
  float acc = 0.f;
  #pragma unroll 4
  for (int t = 0; t < 64; t++){
    int p = pi[b0 + t];
    acc += g_reps[((long)m*NN + p)*DX + j];
  }
  atomicAdd(&g_kmod[m*DX + j], acc);
}
__global__ void k_kpvp(const float* __restrict__ kW, const float* __restrict__ vW){
  int tid = threadIdx.x;
  int m = tid >> 6, j = tid & 63;
  float s1 = 0.f, s2 = 0.f;
  #pragma unroll 8
  for (int k = 0; k < DX; k++){
    float km = g_kmod[m*DX + k] * (1.f/BB);
    s1 += km * kW[j*DX + k];
    s2 += km * vW[j*DX + k];
  }
  g_kp[m*DX + j] = s1;
  g_vp[m*DX + j] = s2;
}
__global__ void __launch_bounds__(64) k_final(
    const float* __restrict__ rep,
    const int* __restrict__ un, const int* __restrict__ pi, const int* __restrict__ ni,
    const float* __restrict__ qW,
    const float* __restrict__ mpW1, const float* __restrict__ mpb1,
    const float* __restrict__ mpW2, const float* __restrict__ mpb2,
    float* __restrict__ out_pos, float* __restrict__ out_neg, float* __restrict__ out_pred)
{
  int b = blockIdx.x, j = threadIdx.x;
  __shared__ float su[DX], sq[DX], sa[DX], sp[DX], sn[DX], sc[MM], red[DX];
  su[j] = rep[(long)un[b]*DX + j];
  sp[j] = rep[(long)pi[b]*DX + j];
  sn[j] = rep[(long)ni[b]*DX + j];
  __syncthreads();
  float q = 0.f;
  #pragma unroll 8
  for (int k = 0; k < DX; k++) q += su[k] * qW[j*DX + k];
  sq[j] = q;
  __syncthreads();
  if (j < MM){
    float s = 0.f;
    #pragma unroll 8
    for (int k = 0; k < DX; k++) s += sq[k] * g_kp[j*DX + k];
    sc[j] = s * 0.125f;
  }
  __syncthreads();
  float mx = fmaxf(fmaxf(sc[0], sc[1]), fmaxf(sc[2], sc[3]));
  float e0 = expf(sc[0]-mx), e1 = expf(sc[1]-mx), e2 = expf(sc[2]-mx), e3 = expf(sc[3]-mx);
  float es = e0 + e1 + e2 + e3;
  float av = (e0*g_vp[0*DX+j] + e1*g_vp[1*DX+j] + e2*g_vp[2*DX+j] + e3*g_vp[3*DX+j]) / es;
  sa[j] = av;
  red[j] = av * sp[j];
  __syncthreads();
  for (int s = 32; s > 0; s >>= 1){ if (j < s) red[j] += red[j+s]; __syncthreads(); }
  if (j == 0) out_pos[b] = red[0];
  __syncthreads();
  red[j] = av * sn[j];
  __syncthreads();
  for (int s = 32; s > 0; s >>= 1){ if (j < s) red[j] += red[j+s]; __syncthreads(); }
  if (j == 0) out_neg[b] = red[0];
  __syncthreads();
  float h = mpb1[j];
  #pragma unroll 8
  for (int k = 0; k < DX; k++) h += sa[k] * mpW1[j*2*DX + k];
  #pragma unroll 8
  for (int k = 0; k < DX; k++) h += sp[k] * mpW1[j*2*DX + DX + k];
  h = lrelu(h);
  red[j] = h * mpW2[j];
  __syncthreads();
  for (int s = 32; s > 0; s >>= 1){ if (j < s) red[j] += red[j+s]; __syncthreads(); }
  if (j == 0) out_pred[b] = red[0] + mpb2[0];
}

// ---------------- host ----------------
extern "C" void kernel_launch(void* const* d_in, const int* in_sizes, int n_in,
                              void* d_out, int out_size)
{
  const float* feats  = (const float*)d_in[0];
  const float* uf     = (const float*)d_in[1];
  const float* userW  = (const float*)d_in[2];
  const float* userb  = (const float*)d_in[3];
  const float* convW  = (const float*)d_in[4];
  const float* convb  = (const float*)d_in[5];
  const float* lin1W  = (const float*)d_in[6];
  const float* lin1b  = (const float*)d_in[7];
  const float* g1W    = (const float*)d_in[8];
  const float* g1b    = (const float*)d_in[9];
  const float* id_emb = (const float*)d_in[10];
  const float* qW     = (const float*)d_in[11];
  const float* kW     = (const float*)d_in[12];
  const float* vW     = (const float*)d_in[13];
  const float* mpW1   = (const float*)d_in[14];
  const float* mpb1   = (const float*)d_in[15];
  const float* mpW2   = (const float*)d_in[16];
  const float* mpb2   = (const float*)d_in[17];
  const int*   eidx   = (const int*)d_in[18];
  const int*   un     = (const int*)d_in[19];
  const int*   pi     = (const int*)d_in[20];
  const int*   ni     = (const int*)d_in[21];
  const int *src = eidx, *dst = eidx + EE;

  float* out      = (float*)d_out;
  float* out_pos  = out;
  float* out_neg  = out + BB;
  float* out_rep  = out + 2*BB;
  float* out_pred = out + 2*BB + (long)NN*DX;

  void* p;
  cudaGetSymbolAddress(&p, g_xb);   __nv_bfloat16* xb  = (__nv_bfloat16*)p;
  cudaGetSymbolAddress(&p, g_hb);   __nv_bfloat16* hb  = (__nv_bfloat16*)p;
  cudaGetSymbolAddress(&p, g_ufb);  __nv_bfloat16* ufb = (__nv_bfloat16*)p;
  cudaGetSymbolAddress(&p, g_uwb);  __nv_bfloat16* uwb = (__nv_bfloat16*)p;
  cudaGetSymbolAddress(&p, g_cwb);  __nv_bfloat16* cwb = (__nv_bfloat16*)p;
  cudaGetSymbolAddress(&p, g_l1b);  __nv_bfloat16* l1b = (__nv_bfloat16*)p;
  cudaGetSymbolAddress(&p, g_g1b);  __nv_bfloat16* g1bw= (__nv_bfloat16*)p;
  cudaGetSymbolAddress(&p, g_xt16); __half* xt16 = (__half*)p;
  cudaGetSymbolAddress(&p, g_agg);  float* agg   = (float*)p;
  cudaGetSymbolAddress(&p, g_xh);   float* xh    = (float*)p;
  cudaGetSymbolAddress(&p, g_reps); float* reps  = (float*)p;

  const int SMB128 = (128*72 + 128*72)*2*2;   // 73728 B
  const int SMB64  = (128*72 + 64*72)*2*2;    // 55296 B
  cudaFuncSetAttribute(k_bgemm<128,1>, cudaFuncAttributeMaxDynamicSharedMemorySize, SMB128);
  cudaFuncSetAttribute(k_bgemm<128,5>, cudaFuncAttributeMaxDynamicSharedMemorySize, SMB128);
  cudaFuncSetAttribute(k_bgemm<64,2>,  cudaFuncAttributeMaxDynamicSharedMemorySize, SMB64);
  cudaFuncSetAttribute(k_bgemm<64,3>,  cudaFuncAttributeMaxDynamicSharedMemorySize, SMB64);

  // (1) prep
  k_prep<<<(MM*N_ITEM*32)/256, 256>>>(feats, uf, userW, convW, lin1W, g1W);
  // (2) user transform (batched over m)
  {
    dim3 g((N_USER+127)/128, 1, MM);
    k_bgemm<128,1><<<g, 256, SMB128>>>(ufb, uwb, agg, nullptr, N_USER,
                                       0, 128L*384, (long)N_USER*DD, userb, DD, nullptr, 0);
  }
  // (3) users normalize -> bf16 planes
  k_norm_users<<<(MM*N_USER*32 + 255)/256, 256>>>();
  // (4) xt16 = x @ convW (fp16-only out, batched)  <-- ncu profile slot
  {
    dim3 g((NN+127)/128, 1, MM);
    k_bgemm<128,5><<<g, 256, SMB128>>>(xb, cwb, nullptr, xt16, NN,
                                       (long)NN*256, 128L*384, (long)NN*DD,
                                       nullptr, 0, nullptr, 0);
  }
  // (5) xh = lrelu(x @ lin1W^T + b) + id_emb (batched)
  {
    dim3 g((NN+127)/128, 1, MM);
    k_bgemm<64,2><<<g, 256, SMB64>>>(xb, l1b, xh, nullptr, NN,
                                     (long)NN*256, 64L*384, (long)NN*DX,
                                     lin1b, DX, id_emb, 0);
  }
  // CSR build (once)
  k_deg    <<<(EE+255)/256, 256>>>(src, dst);
  k_scan   <<<1, SCAN_T>>>();
  k_scatter<<<(EE+255)/256, 256>>>(src, dst);

  // edge pipeline per modality (fp16 xt slice hot in L2)
  for (int m = 0; m < MM; m++){
    const __half* xt16m = xt16 + (long)m*NN*DD;
    k_ipwm   <<<(EE*8 + 255)/256, 256>>>(xt16m);
    k_nodeagg<<<(NN*32 + 255)/256, 256>>>(xt16m, convb + m*DD, hb + (long)m*NN*256);
  }

  // reps = lrelu(h @ g1W^T + g1b + xh) (batched)
  {
    dim3 g((NN+127)/128, 1, MM);
    k_bgemm<64,3><<<g, 256, SMB64>>>(hb, g1bw, reps, nullptr, NN,
                                     (long)NN*256, 64L*384, (long)NN*DX,
                                     g1b, DX, xh, (long)NN*DX);
  }

  k_mean<<<(NN*DX + 255)/256, 256>>>(out_rep);
  k_kmod<<<dim3(BB/64, MM), 64>>>(pi);
  k_kpvp<<<1, 256>>>(kW, vW);
  k_final<<<BB, 64>>>(out_rep, un, pi, ni, qW, mpW1, mpb1, mpW2, mpb2,
                      out_pos, out_neg, out_pred);
}

// round 16
// speedup vs baseline: 1.1305x; 1.0147x over previous
#include <cuda_runtime.h>
#include <cuda_bf16.h>
#include <cuda_fp16.h>
#include <cstdint>
#include <math.h>

#define MM 4
#define N_ITEM 40000
#define N_USER 10000
#define NN 50000
#define DD 128
#define DX 64
#define EE 400000
#define BB 4096

// ---------------- scratch (device globals; allocation-free) ----------------
__device__ __nv_bfloat16 g_xb [(long)MM*NN*256];   // x hi|lo planes
__device__ __nv_bfloat16 g_hb [(long)MM*NN*256];   // h hi|lo planes
__device__ __nv_bfloat16 g_ufb[(long)N_USER*256];
__device__ __nv_bfloat16 g_uwb[MM*128*384];
__device__ __nv_bfloat16 g_cwb[MM*128*384];
__device__ __nv_bfloat16 g_l1b[MM*64*384];
__device__ __nv_bfloat16 g_g1b[MM*64*384];
__device__ __half g_xt16[(long)MM*NN*DD];          // fp16 xt (edge phase only)
__device__ float g_agg [MM*NN*DD];   // fp32 temp (usergemm out)
__device__ float g_xh  [MM*NN*DX];
__device__ float g_reps[MM*NN*DX];
__device__ float g_w   [EE];         // logits in CSR position order
__device__ float g_deg [NN];
__device__ float g_dinv[NN];
__device__ int   g_degD[NN];
__device__ int   g_off [NN+1];
__device__ int   g_cur [NN];
__device__ int   g_srcs[EE];
__device__ int   g_dsts[EE];
__device__ float g_kmod[MM*DX];
__device__ float g_kp  [MM*DX];
__device__ float g_vp  [MM*DX];

__device__ __forceinline__ float lrelu(float x){ return x > 0.f ? x : 0.01f*x; }
__device__ __forceinline__ float wsum(float v){
  #pragma unroll
  for (int o = 16; o; o >>= 1) v += __shfl_xor_sync(0xffffffffu, v, o);
  return v;
}
__device__ __forceinline__ float wmaxr(float v){
  #pragma unroll
  for (int o = 16; o; o >>= 1) v = fmaxf(v, __shfl_xor_sync(0xffffffffu, v, o));
  return v;
}
__device__ __forceinline__ __nv_bfloat16 hilo(float v, bool lo){
  __nv_bfloat16 h = __float2bfloat16(v);
  return lo ? __float2bfloat16(v - __bfloat162float(h)) : h;
}
__device__ __forceinline__ void put4(__nv_bfloat16* dst, float4 v, float rn){
  float a0=v.x*rn, a1=v.y*rn, a2=v.z*rn, a3=v.w*rn;
  __nv_bfloat16 h[4] = {__float2bfloat16(a0),__float2bfloat16(a1),
                        __float2bfloat16(a2),__float2bfloat16(a3)};
  __nv_bfloat16 l[4] = {
    __float2bfloat16(a0-__bfloat162float(h[0])), __float2bfloat16(a1-__bfloat162float(h[1])),
    __float2bfloat16(a2-__bfloat162float(h[2])), __float2bfloat16(a3-__bfloat162float(h[3]))};
  *(uint2*)dst = *(uint2*)h;
  *(uint2*)(dst+128) = *(uint2*)l;
}

// ---------------- MMA + cp.async + ldmatrix primitives ----------------
__device__ __forceinline__ void mma16816(float* d, const uint32_t* a, const uint32_t* b){
  asm volatile("mma.sync.aligned.m16n8k16.row.col.f32.bf16.bf16.f32 "
    "{%0,%1,%2,%3}, {%4,%5,%6,%7}, {%8,%9}, {%0,%1,%2,%3};"
    : "+f"(d[0]), "+f"(d[1]), "+f"(d[2]), "+f"(d[3])
    : "r"(a[0]), "r"(a[1]), "r"(a[2]), "r"(a[3]), "r"(b[0]), "r"(b[1]));
}
__device__ __forceinline__ uint32_t smem_u32(const void* p){
  uint32_t a;
  asm("{ .reg .u64 t; cvta.to.shared.u64 t, %1; cvt.u32.u64 %0, t; }" : "=r"(a) : "l"(p));
  return a;
}
__device__ __forceinline__ void cpasync16(uint32_t sdst, const void* gsrc, bool pred){
  int sz = pred ? 16 : 0;
  asm volatile("cp.async.cg.shared.global [%0], [%1], 16, %2;"
               :: "r"(sdst), "l"(gsrc), "r"(sz));
}
#define CP_COMMIT() asm volatile("cp.async.commit_group;" ::: "memory")
#define CP_WAIT1()  asm volatile("cp.async.wait_group 1;" ::: "memory")
#define CP_WAIT0()  asm volatile("cp.async.wait_group 0;" ::: "memory")
#define LDSM4(r0,r1,r2,r3,addr) \
  asm volatile("ldmatrix.sync.aligned.m8n8.x4.shared.b16 {%0,%1,%2,%3}, [%4];" \
    : "=r"(r0),"=r"(r1),"=r"(r2),"=r"(r3) : "r"(addr))

// ---- bf16 HMMA GEMM, K_eff=384, cp.async double-buffered, ldmatrix frags ---
// EPI 0: none->fp32 | 1: tanh(+bias)->fp32 | 2: lrelu(+bias)+add->fp32
// EPI 3: lrelu(+bias+add)->fp32 | 5: none->fp16 ONLY (C16)
template<int BN, int EPI>
__global__ void __launch_bounds__(256,2) k_bgemm(
    const __nv_bfloat16* __restrict__ A, const __nv_bfloat16* __restrict__ Bw,
    float* __restrict__ C, __half* __restrict__ C16, int M,
    long sA, long sB, long sC,
    const float* __restrict__ bias, long sBias,
    const float* __restrict__ add, long sAdd)
{
  constexpr int P = 72;
  constexpr int ASZ = 128*P, BSZ = BN*P, STG = ASZ + BSZ;
  constexpr int NF = BN/16;
  constexpr int LB = BN/32;
  extern __shared__ __nv_bfloat16 sm[];
  int z = blockIdx.z;
  A += (long)z*sA; Bw += (long)z*sB;
  if (EPI != 5) C   += (long)z*sC;
  if (EPI == 5) C16 += (long)z*sC;
  if (EPI == 1 || EPI == 2 || EPI == 3) bias += (long)z*sBias;
  if (EPI == 2 || EPI == 3)             add  += (long)z*sAdd;
  int m0 = blockIdx.x*128;
  int tid = threadIdx.x, lane = tid & 31, wid = tid >> 5;
  uint32_t smb = smem_u32(sm);

  auto aload = [&](int t, int buf){
    int cb = ((t & 4) << 5) | ((t & 1) << 6);   // {0,64,0,64,128,192}
    #pragma unroll
    for (int i = 0; i < 4; i++){
      int idx = tid + i*256;
      int r = idx >> 3, c8 = (idx & 7)*8;
      bool inb = (m0 + r) < M;
      const __nv_bfloat16* gp = A + (inb ? ((long)(m0+r)*256 + cb + c8) : 0);
      cpasync16(smb + (uint32_t)(buf*STG + r*P + c8)*2, gp, inb);
    }
    #pragma unroll
    for (int i = 0; i < LB; i++){
      int idx = tid + i*256;
      int r = idx >> 3, c8 = (idx & 7)*8;
      cpasync16(smb + (uint32_t)(buf*STG + ASZ + r*P + c8)*2,
                Bw + (long)r*384 + t*64 + c8, true);
    }
  };

  aload(0, 0);
  CP_COMMIT();

  int wm = (wid & 3) << 5;
  int wn = (wid >> 2) * (BN/2);
  int lr = lane >> 2, lc = (lane & 3) << 1;
  int grp = lane >> 3, r8 = lane & 7;
  uint32_t offA[2], offB[NF/2];
  #pragma unroll
  for (int mi = 0; mi < 2; mi++)
    offA[mi] = (uint32_t)((wm + mi*16 + (grp & 1)*8 + r8)*P + (grp >> 1)*8);
  #pragma unroll
  for (int pp = 0; pp < NF/2; pp++)
    offB[pp] = (uint32_t)(ASZ + (wn + pp*16 + (grp >> 1)*8 + r8)*P + (grp & 1)*8);

  float acc[2][NF][4];
  #pragma unroll
  for (int i = 0; i < 2; i++)
    #pragma unroll
    for (int j = 0; j < NF; j++)
      #pragma unroll
      for (int q = 0; q < 4; q++) acc[i][j][q] = 0.f;

  #pragma unroll
  for (int t = 0; t < 6; t++){
    if (t < 5){ aload(t+1, (t+1)&1); CP_COMMIT(); CP_WAIT1(); }
    else      { CP_WAIT0(); }
    __syncthreads();
    uint32_t tb = smb + (uint32_t)((t&1)*STG)*2;
    #pragma unroll
    for (int k0 = 0; k0 < 64; k0 += 16){
      uint32_t a[2][4];
      #pragma unroll
      for (int mi = 0; mi < 2; mi++)
        LDSM4(a[mi][0], a[mi][1], a[mi][2], a[mi][3], tb + (offA[mi] + k0)*2);
      uint32_t b[NF][2];
      #pragma unroll
      for (int pp = 0; pp < NF/2; pp++)
        LDSM4(b[2*pp][0], b[2*pp][1], b[2*pp+1][0], b[2*pp+1][1], tb + (offB[pp] + k0)*2);
      #pragma unroll
      for (int nf = 0; nf < NF; nf++){
        mma16816(acc[0][nf], a[0], b[nf]);
        mma16816(acc[1][nf], a[1], b[nf]);
      }
    }
    __syncthreads();
  }

  #pragma unroll
  for (int mi = 0; mi < 2; mi++){
    #pragma unroll
    for (int h = 0; h < 2; h++){
      int row = m0 + wm + mi*16 + lr + h*8;
      if (row >= M) continue;
      #pragma unroll
      for (int nf = 0; nf < NF; nf++){
        int n = wn + nf*8 + lc;
        float x0 = acc[mi][nf][h*2+0];
        float x1 = acc[mi][nf][h*2+1];
        if (EPI == 1){ x0 = tanhf(x0 + bias[n]); x1 = tanhf(x1 + bias[n+1]); }
        else if (EPI == 2){
          x0 = lrelu(x0 + bias[n])   + add[(long)row*BN + n];
          x1 = lrelu(x1 + bias[n+1]) + add[(long)row*BN + n+1];
        } else if (EPI == 3){
          x0 = lrelu(x0 + bias[n]   + add[(long)row*BN + n]);
          x1 = lrelu(x1 + bias[n+1] + add[(long)row*BN + n+1]);
        }
        if (EPI == 5)
          *(__half2*)(C16 + (long)row*BN + n) = __float22half2_rn(make_float2(x0, x1));
        else
          *(float2*)(C + (long)row*BN + n) = make_float2(x0, x1);
      }
    }
  }
}

// ------- k_prep: items normalize->bf16 planes + all input conversions -------
#define CV0 (N_USER*256)
#define WU  (MM*128*384)
#define WL  (MM*64*384)
#define CV1 (CV0 + WU)
#define CV2 (CV1 + WU)
#define CV3 (CV2 + WL)
#define CV4 (CV3 + WL)
__global__ void k_prep(const float* __restrict__ feats, const float* __restrict__ uf,
                       const float* __restrict__ userW, const float* __restrict__ convW,
                       const float* __restrict__ lin1W, const float* __restrict__ g1W){
  long g = (long)blockIdx.x*256 + threadIdx.x;
  if (g < NN){ g_deg[g] = 0.f; g_degD[g] = 0; }
  long w = g >> 5; int lane = (int)(g & 31);
  if (w < (long)MM*N_ITEM){
    int m = (int)(w / N_ITEM), i = (int)(w - (long)m*N_ITEM);
    const float* in = feats + ((long)m*N_ITEM + i)*DD;
    float4 v = *(const float4*)(in + lane*4);
    float ss = wsum(v.x*v.x + v.y*v.y + v.z*v.z + v.w*v.w);
    float rn = 1.f / fmaxf(sqrtf(ss), 1e-12f);
    put4(g_xb + ((long)m*NN + i)*256 + lane*4, v, rn);
  }
  if (g < CV0){
    int r = (int)(g >> 8), c = (int)(g & 255);
    g_ufb[g] = hilo(uf[r*128 + (c & 127)], c >= 128);
  } else if (g < CV1){
    long j = g - CV0;
    int m = (int)(j/49152); int r2 = (int)(j%49152);
    int n = r2/384, kp = r2%384, sel = kp>>7, kk = kp&127;
    g_uwb[j] = hilo(userW[(long)m*16384 + n*128 + kk], sel == 1);
  } else if (g < CV2){
    long j = g - CV1;
    int m = (int)(j/49152); int r2 = (int)(j%49152);
    int n = r2/384, kp = r2%384, sel = kp>>7, kk = kp&127;
    g_cwb[j] = hilo(convW[(long)m*16384 + kk*128 + n], sel == 1);
  } else if (g < CV3){
    long j = g - CV2;
    int m = (int)(j/24576); int r2 = (int)(j%24576);
    int n = r2/384, kp = r2%384, sel = kp>>7, kk = kp&127;
    g_l1b[j] = hilo(lin1W[(long)m*8192 + n*128 + kk], sel == 1);
  } else if (g < CV4){
    long j = g - CV3;
    int m = (int)(j/24576); int r2 = (int)(j%24576);
    int n = r2/384, kp = r2%384, sel = kp>>7, kk = kp&127;
    g_g1b[j] = hilo(g1W[(long)m*8192 + n*128 + kk], sel == 1);
  }
}
__global__ void k_norm_users(){
  int g = blockIdx.x*256 + threadIdx.x;
  int w = g >> 5, lane = g & 31;
  if (w >= MM*N_USER) return;
  int m = w / N_USER, i = w - m*N_USER;
  const float* in = g_agg + ((long)m*N_USER + i)*DD;
  float4 v = *(const float4*)(in + lane*4);
  float ss = wsum(v.x*v.x + v.y*v.y + v.z*v.z + v.w*v.w);
  float rn = 1.f / fmaxf(sqrtf(ss), 1e-12f);
  put4(g_xb + ((long)m*NN + N_ITEM + i)*256 + lane*4, v, rn);
}

// ---------------- CSR build ----------------
__global__ void k_deg(const int* __restrict__ src, const int* __restrict__ dst){
  int e = blockIdx.x*256 + threadIdx.x;
  if (e < EE){ atomicAdd(&g_deg[src[e]], 1.f); atomicAdd(&g_degD[dst[e]], 1); }
}
#define SCAN_T 1024
__global__ void __launch_bounds__(SCAN_T) k_scan(){
  __shared__ int ps[SCAN_T];
  int t = threadIdx.x;
  const int C = (NN + SCAN_T - 1)/SCAN_T;
  int lo = t*C, hi = lo+C < NN ? lo+C : NN;
  int s = 0;
  for (int i = lo; i < hi; i++){
    s += g_degD[i];
    float d = g_deg[i];
    g_dinv[i] = d > 0.f ? 1.f/sqrtf(d) : 0.f;
  }
  ps[t] = s; __syncthreads();
  for (int off = 1; off < SCAN_T; off <<= 1){
    int v = (t >= off) ? ps[t-off] : 0;
    __syncthreads();
    ps[t] += v;
    __syncthreads();
  }
  int run = t ? ps[t-1] : 0;
  for (int i = lo; i < hi; i++){ int d = g_degD[i]; g_off[i] = run; g_cur[i] = run; run += d; }
  if (t == SCAN_T-1) g_off[NN] = run;
}
__global__ void k_scatter(const int* __restrict__ src, const int* __restrict__ dst){
  int e = blockIdx.x*256 + threadIdx.x;
  if (e < EE){
    int d = dst[e];
    int p = atomicAdd(&g_cur[d], 1);
    g_srcs[p] = src[e];
    g_dsts[p] = d;
  }
}

// ------- edge logits (CSR order, fp16 rows): 8 lanes/edge, 4 edges/warp -----
__global__ void __launch_bounds__(256) k_ipwm(const __half* __restrict__ xt16){
  int gw = (blockIdx.x << 3) | (threadIdx.x >> 5);
  int lane = threadIdx.x & 31;
  int sub = lane >> 3, l8 = lane & 7;
  int i = (gw << 2) | sub;
  if (i >= EE) return;
  int s = g_srcs[i], d = g_dsts[i];
  const __half* ps = xt16 + (long)s*DD;
  const __half* pd = xt16 + (long)d*DD;
  float acc = 0.f;
  #pragma unroll
  for (int c = 0; c < 2; c++){
    uint4 a4 = *(const uint4*)(ps + c*64 + l8*8);
    uint4 b4 = *(const uint4*)(pd + c*64 + l8*8);
    const __half2* ah = (const __half2*)&a4;
    const __half2* bh = (const __half2*)&b4;
    #pragma unroll
    for (int j = 0; j < 4; j++){
      float2 a = __half22float2(ah[j]);
      float2 b = __half22float2(bh[j]);
      acc += b.x*lrelu(a.x) + b.y*lrelu(a.y);
    }
  }
  #pragma unroll
  for (int o = 4; o; o >>= 1) acc += __shfl_xor_sync(0xffffffffu, acc, o);
  if (l8 == 0){
    float di = g_dinv[s];
    g_w[i] = acc / (1.f + expf(-di*acc));
  }
}

// fused per-dst segment softmax + aggregate; register-cached w/src, parallel exp
__global__ void __launch_bounds__(256) k_nodeagg(const __half* __restrict__ xt16,
                                                 const float* __restrict__ cb,
                                                 __nv_bfloat16* __restrict__ hb){
  int g = blockIdx.x*256 + threadIdx.x;
  int n = g >> 5, lane = g & 31;
  if (n >= NN) return;
  int o0 = g_off[n], o1 = g_off[n+1];
  int deg = o1 - o0;
  // cache first 32 edges in registers (coalesced)
  float wv = -3.4e38f; int sv = 0;
  if (lane < deg){ wv = g_w[o0 + lane]; sv = g_srcs[o0 + lane]; }
  // segment max
  float wm = wv;
  for (int base = 32; base < deg; base += 32){
    int ii = base + lane;
    if (ii < deg) wm = fmaxf(wm, g_w[o0 + ii]);
  }
  wm = wmaxr(wm);
  // exp-sum (one expf per lane, parallel)
  float e0 = (lane < deg) ? expf(wv - wm) : 0.f;
  float es_l = e0;
  for (int base = 32; base < deg; base += 32){
    int ii = base + lane;
    if (ii < deg) es_l += expf(g_w[o0 + ii] - wm);
  }
  float es = wsum(es_l);
  float rs = 1.f / (es + 1e-16f);
  float att_l = e0 * rs;            // this lane's attention weight
  // aggregate first chunk: broadcast att/src from registers, 4 gathers in flight
  float4 acc = make_float4(0,0,0,0);
  int c0 = deg < 32 ? deg : 32;
  int i = 0;
  for (; i + 4 <= c0; i += 4){
    float t0 = __shfl_sync(0xffffffffu, att_l, i);
    float t1 = __shfl_sync(0xffffffffu, att_l, i+1);
    float t2 = __shfl_sync(0xffffffffu, att_l, i+2);
    float t3 = __shfl_sync(0xffffffffu, att_l, i+3);
    int s0 = __shfl_sync(0xffffffffu, sv, i);
    int s1 = __shfl_sync(0xffffffffu, sv, i+1);
    int s2 = __shfl_sync(0xffffffffu, sv, i+2);
    int s3 = __shfl_sync(0xffffffffu, sv, i+3);
    uint2 v0 = *(const uint2*)(xt16 + (long)s0*DD + lane*4);
    uint2 v1 = *(const uint2*)(xt16 + (long)s1*DD + lane*4);
    uint2 v2 = *(const uint2*)(xt16 + (long)s2*DD + lane*4);
    uint2 v3 = *(const uint2*)(xt16 + (long)s3*DD + lane*4);
    float2 a00 = __half22float2(*(__half2*)&v0.x), a01 = __half22float2(*(__half2*)&v0.y);
    float2 a10 = __half22float2(*(__half2*)&v1.x), a11 = __half22float2(*(__half2*)&v1.y);
    float2 a20 = __half22float2(*(__half2*)&v2.x), a21 = __half22float2(*(__half2*)&v2.y);
    float2 a30 = __half22float2(*(__half2*)&v3.x), a31 = __half22float2(*(__half2*)&v3.y);
    acc.x += t0*a00.x + t1*a10.x + t2*a20.x + t3*a30.x;
    acc.y += t0*a00.y + t1*a10.y + t2*a20.y + t3*a30.y;
    acc.z += t0*a01.x + t1*a11.x + t2*a21.x + t3*a31.x;
    acc.w += t0*a01.y + t1*a11.y + t2*a21.y + t3*a31.y;
  }
  for (; i < c0; i++){
    float att = __shfl_sync(0xffffffffu, att_l, i);
    int s = __shfl_sync(0xffffffffu, sv, i);
    uint2 av = *(const uint2*)(xt16 + (long)s*DD + lane*4);
    float2 a0 = __half22float2(*(__half2*)&av.x);
    float2 a1 = __half22float2(*(__half2*)&av.y);
    acc.x += att*a0.x; acc.y += att*a0.y; acc.z += att*a1.x; acc.w += att*a1.y;
  }
  // rare tail (deg > 32)
  for (int base = 32; base < deg; base += 32){
    int ii = base + lane;
    float w2 = 0.f; int s2 = 0;
    bool ok = ii < deg;
    if (ok){ w2 = g_w[o0 + ii]; s2 = g_srcs[o0 + ii]; }
    float a2 = ok ? expf(w2 - wm) * rs : 0.f;
    int cnt = (deg - base) < 32 ? (deg - base) : 32;
    for (int j = 0; j < cnt; j++){
      float att = __shfl_sync(0xffffffffu, a2, j);
      int s = __shfl_sync(0xffffffffu, s2, j);
      uint2 av = *(const uint2*)(xt16 + (long)s*DD + lane*4);
      float2 a0 = __half22float2(*(__half2*)&av.x);
      float2 a1 = __half22float2(*(__half2*)&av.y);
      acc.x += att*a0.x; acc.y += att*a0.y; acc.z += att*a1.x; acc.w += att*a1.y;
    }
  }
  // epilogue: + convb, l2norm, lrelu -> bf16 hi|lo
  float4 b4 = *(const float4*)(cb + lane*4);
  acc.x += b4.x; acc.y += b4.y; acc.z += b4.z; acc.w += b4.w;
  float ss = acc.x*acc.x + acc.y*acc.y + acc.z*acc.z + acc.w*acc.w;
  ss = wsum(ss);
  float rn = 1.f / fmaxf(sqrtf(ss), 1e-12f);
  float4 o;
  o.x = lrelu(acc.x*rn); o.y = lrelu(acc.y*rn);
  o.z = lrelu(acc.z*rn); o.w = lrelu(acc.w*rn);
  put4(hb + (long)n*256 + lane*4, o, 1.f);
}

// ---------------- tail ----------------
__global__ void k_mean(float* __restrict__ out_rep){
  int i = blockIdx.x*256 + threadIdx.x;
  if (i < MM*DX) g_kmod[i] = 0.f;
  if (i < NN*DX)
    out_rep[i] = 0.25f * (g_reps[i] + g_reps[(long)NN*DX + i]
                        + g_reps[2L*NN*DX + i] + g_reps[3L*NN*DX + i]);
}
__global__ void __launch_bounds__(64) k_kmod(const int* __restrict__ pi){
  int m = blockIdx.y, j = threadIdx.x;
  int b0 = blockIdx.x * 64;
  float acc = 0.f;
  #pragma unroll 4
  for (int t = 0; t < 64; t++){
    int p = pi[b0 + t];
    acc += g_reps[((long)m*NN + p)*DX + j];
  }
  atomicAdd(&g_kmod[m*DX + j], acc);
}
__global__ void k_kpvp(const float* __restrict__ kW, const float* __restrict__ vW){
  int tid = threadIdx.x;
  int m = tid >> 6, j = tid & 63;
  float s1 = 0.f, s2 = 0.f;
  #pragma unroll 8
  for (int k = 0; k < DX; k++){
    float km = g_kmod[m*DX + k] * (1.f/BB);
    s1 += km * kW[j*DX + k];
    s2 += km * vW[j*DX + k];
  }
  g_kp[m*DX + j] = s1;
  g_vp[m*DX + j] = s2;
}
__global__ void __launch_bounds__(64) k_final(
    const float* __restrict__ rep,
    const int* __restrict__ un, const int* __restrict__ pi, const int* __restrict__ ni,
    const float* __restrict__ qW,
    const float* __restrict__ mpW1, const float* __restrict__ mpb1,
    const float* __restrict__ mpW2, const float* __restrict__ mpb2,
    float* __restrict__ out_pos, float* __restrict__ out_neg, float* __restrict__ out_pred)
{
  int b = blockIdx.x, j = threadIdx.x;
  __shared__ float su[DX], sq[DX], sa[DX], sp[DX], sn[DX], sc[MM], red[DX];
  su[j] = rep[(long)un[b]*DX + j];
  sp[j] = rep[(long)pi[b]*DX + j];
  sn[j] = rep[(long)ni[b]*DX + j];
  __syncthreads();
  float q = 0.f;
  #pragma unroll 8
  for (int k = 0; k < DX; k++) q += su[k] * qW[j*DX + k];
  sq[j] = q;
  __syncthreads();
  if (j < MM){
    float s = 0.f;
    #pragma unroll 8
    for (int k = 0; k < DX; k++) s += sq[k] * g_kp[j*DX + k];
    sc[j] = s * 0.125f;
  }
  __syncthreads();
  float mx = fmaxf(fmaxf(sc[0], sc[1]), fmaxf(sc[2], sc[3]));
  float e0 = expf(sc[0]-mx), e1 = expf(sc[1]-mx), e2 = expf(sc[2]-mx), e3 = expf(sc[3]-mx);
  float es = e0 + e1 + e2 + e3;
  float av = (e0*g_vp[0*DX+j] + e1*g_vp[1*DX+j] + e2*g_vp[2*DX+j] + e3*g_vp[3*DX+j]) / es;
  sa[j] = av;
  red[j] = av * sp[j];
  __syncthreads();
  for (int s = 32; s > 0; s >>= 1){ if (j < s) red[j] += red[j+s]; __syncthreads(); }
  if (j == 0) out_pos[b] = red[0];
  __syncthreads();
  red[j] = av * sn[j];
  __syncthreads();
  for (int s = 32; s > 0; s >>= 1){ if (j < s) red[j] += red[j+s]; __syncthreads(); }
  if (j == 0) out_neg[b] = red[0];
  __syncthreads();
  float h = mpb1[j];
  #pragma unroll 8
  for (int k = 0; k < DX; k++) h += sa[k] * mpW1[j*2*DX + k];
  #pragma unroll 8
  for (int k = 0; k < DX; k++) h += sp[k] * mpW1[j*2*DX + DX + k];
  h = lrelu(h);
  red[j] = h * mpW2[j];
  __syncthreads();
  for (int s = 32; s > 0; s >>= 1){ if (j < s) red[j] += red[j+s]; __syncthreads(); }
  if (j == 0) out_pred[b] = red[0] + mpb2[0];
}

// ---------------- host ----------------
extern "C" void kernel_launch(void* const* d_in, const int* in_sizes, int n_in,
                              void* d_out, int out_size)
{
  const float* feats  = (const float*)d_in[0];
  const float* uf     = (const float*)d_in[1];
  const float* userW  = (const float*)d_in[2];
  const float* userb  = (const float*)d_in[3];
  const float* convW  = (const float*)d_in[4];
  const float* convb  = (const float*)d_in[5];
  const float* lin1W  = (const float*)d_in[6];
  const float* lin1b  = (const float*)d_in[7];
  const float* g1W    = (const float*)d_in[8];
  const float* g1b    = (const float*)d_in[9];
  const float* id_emb = (const float*)d_in[10];
  const float* qW     = (const float*)d_in[11];
  const float* kW     = (const float*)d_in[12];
  const float* vW     = (const float*)d_in[13];
  const float* mpW1   = (const float*)d_in[14];
  const float* mpb1   = (const float*)d_in[15];
  const float* mpW2   = (const float*)d_in[16];
  const float* mpb2   = (const float*)d_in[17];
  const int*   eidx   = (const int*)d_in[18];
  const int*   un     = (const int*)d_in[19];
  const int*   pi     = (const int*)d_in[20];
  const int*   ni     = (const int*)d_in[21];
  const int *src = eidx, *dst = eidx + EE;

  float* out      = (float*)d_out;
  float* out_pos  = out;
  float* out_neg  = out + BB;
  float* out_rep  = out + 2*BB;
  float* out_pred = out + 2*BB + (long)NN*DX;

  void* p;
  cudaGetSymbolAddress(&p, g_xb);   __nv_bfloat16* xb  = (__nv_bfloat16*)p;
  cudaGetSymbolAddress(&p, g_hb);   __nv_bfloat16* hb  = (__nv_bfloat16*)p;
  cudaGetSymbolAddress(&p, g_ufb);  __nv_bfloat16* ufb = (__nv_bfloat16*)p;
  cudaGetSymbolAddress(&p, g_uwb);  __nv_bfloat16* uwb = (__nv_bfloat16*)p;
  cudaGetSymbolAddress(&p, g_cwb);  __nv_bfloat16* cwb = (__nv_bfloat16*)p;
  cudaGetSymbolAddress(&p, g_l1b);  __nv_bfloat16* l1b = (__nv_bfloat16*)p;
  cudaGetSymbolAddress(&p, g_g1b);  __nv_bfloat16* g1bw= (__nv_bfloat16*)p;
  cudaGetSymbolAddress(&p, g_xt16); __half* xt16 = (__half*)p;
  cudaGetSymbolAddress(&p, g_agg);  float* agg   = (float*)p;
  cudaGetSymbolAddress(&p, g_xh);   float* xh    = (float*)p;
  cudaGetSymbolAddress(&p, g_reps); float* reps  = (float*)p;

  const int SMB128 = (128*72 + 128*72)*2*2;   // 73728 B
  const int SMB64  = (128*72 + 64*72)*2*2;    // 55296 B
  cudaFuncSetAttribute(k_bgemm<128,1>, cudaFuncAttributeMaxDynamicSharedMemorySize, SMB128);
  cudaFuncSetAttribute(k_bgemm<128,5>, cudaFuncAttributeMaxDynamicSharedMemorySize, SMB128);
  cudaFuncSetAttribute(k_bgemm<64,2>,  cudaFuncAttributeMaxDynamicSharedMemorySize, SMB64);
  cudaFuncSetAttribute(k_bgemm<64,3>,  cudaFuncAttributeMaxDynamicSharedMemorySize, SMB64);

  // (1) prep
  k_prep<<<(MM*N_ITEM*32)/256, 256>>>(feats, uf, userW, convW, lin1W, g1W);
  // (2) user transform (batched over m)
  {
    dim3 g((N_USER+127)/128, 1, MM);
    k_bgemm<128,1><<<g, 256, SMB128>>>(ufb, uwb, agg, nullptr, N_USER,
                                       0, 128L*384, (long)N_USER*DD, userb, DD, nullptr, 0);
  }
  // (3) users normalize -> bf16 planes
  k_norm_users<<<(MM*N_USER*32 + 255)/256, 256>>>();
  // (4) xt16 = x @ convW (fp16-only out, batched)  <-- ncu profile slot
  {
    dim3 g((NN+127)/128, 1, MM);
    k_bgemm<128,5><<<g, 256, SMB128>>>(xb, cwb, nullptr, xt16, NN,
                                       (long)NN*256, 128L*384, (long)NN*DD,
                                       nullptr, 0, nullptr, 0);
  }
  // (5) xh = lrelu(x @ lin1W^T + b) + id_emb (batched)
  {
    dim3 g((NN+127)/128, 1, MM);
    k_bgemm<64,2><<<g, 256, SMB64>>>(xb, l1b, xh, nullptr, NN,
                                     (long)NN*256, 64L*384, (long)NN*DX,
                                     lin1b, DX, id_emb, 0);
  }
  // CSR build (once)
  k_deg    <<<(EE+255)/256, 256>>>(src, dst);
  k_scan   <<<1, SCAN_T>>>();
  k_scatter<<<(EE+255)/256, 256>>>(src, dst);

  // edge pipeline per modality (fp16 xt slice hot in L2)
  for (int m = 0; m < MM; m++){
    const __half* xt16m = xt16 + (long)m*NN*DD;
    k_ipwm   <<<(EE*8 + 255)/256, 256>>>(xt16m);
    k_nodeagg<<<(NN*32 + 255)/256, 256>>>(xt16m, convb + m*DD, hb + (long)m*NN*256);
  }

  // reps = lrelu(h @ g1W^T + g1b + xh) (batched)
  {
    dim3 g((NN+127)/128, 1, MM);
    k_bgemm<64,3><<<g, 256, SMB64>>>(hb, g1bw, reps, nullptr, NN,
                                     (long)NN*256, 64L*384, (long)NN*DX,
                                     g1b, DX, xh, (long)NN*DX);
  }

  k_mean<<<(NN*DX + 255)/256, 256>>>(out_rep);
  k_kmod<<<dim3(BB/64, MM), 64>>>(pi);
  k_kpvp<<<1, 256>>>(kW, vW);
  k_final<<<BB, 64>>>(out_rep, un, pi, ni, qW, mpW1, mpb1, mpW2, mpb2,
                      out_pos, out_neg, out_pred);
}